// round 1
// baseline (speedup 1.0000x reference)
#include <cuda_runtime.h>
#include <math.h>

// Problem constants
#define B_ 8
#define T_ 2048
#define D_ 128
#define L_ 4
#define H_ 2
#define HD_ 64
#define BT_ (B_ * T_)          // 16384 rows
#define EPS_ 1e-8f

// ---------------------------------------------------------------------------
// Scratch buffers (allocation-free: __device__ globals)
// ---------------------------------------------------------------------------
__device__ float g_x [BT_ * D_];
__device__ float g_n [BT_ * D_];
__device__ float g_u [BT_ * D_];
__device__ float g_v [BT_ * D_];
__device__ float g_q [BT_ * D_];
__device__ float g_k [BT_ * D_];
__device__ float g_av[BT_ * D_];
__device__ float g_t [BT_ * D_];

// ---------------------------------------------------------------------------
// Block-wide sum over 128 threads (one value per thread)
// ---------------------------------------------------------------------------
__device__ __forceinline__ float block_sum128(float v) {
    __shared__ float ws[4];
    #pragma unroll
    for (int o = 16; o > 0; o >>= 1) v += __shfl_down_sync(0xffffffffu, v, o);
    if ((threadIdx.x & 31) == 0) ws[threadIdx.x >> 5] = v;
    __syncthreads();
    float s = ws[0] + ws[1] + ws[2] + ws[3];
    __syncthreads();
    return s;
}

// ---------------------------------------------------------------------------
// Embedding gather + add positional + RMSNorm
// grid = BT_, block = 128
// ---------------------------------------------------------------------------
__global__ void embed_rms_kernel(const int* __restrict__ seq,
                                 const float* __restrict__ item,
                                 const float* __restrict__ pos,
                                 const float* __restrict__ sc,
                                 float* __restrict__ out) {
    int row = blockIdx.x;
    int t = row & (T_ - 1);            // row % T_
    int d = threadIdx.x;
    int id = seq[row];
    float v = item[(size_t)id * D_ + d] + pos[(size_t)(t + 1) * D_ + d];
    float s = block_sum128(v * v);
    float r = rsqrtf(s * (1.0f / D_) + EPS_);
    out[(size_t)row * D_ + d] = v * r * sc[d];
}

// ---------------------------------------------------------------------------
// RMSNorm: out = in * rsqrt(mean(in^2)+eps) * scale
// grid = BT_, block = 128
// ---------------------------------------------------------------------------
__global__ void rms_kernel(const float* __restrict__ in,
                           const float* __restrict__ sc,
                           float* __restrict__ out) {
    int row = blockIdx.x;
    int d = threadIdx.x;
    float v = in[(size_t)row * D_ + d];
    float s = block_sum128(v * v);
    float r = rsqrtf(s * (1.0f / D_) + EPS_);
    out[(size_t)row * D_ + d] = v * r * sc[d];
}

// ---------------------------------------------------------------------------
// RMSNorm then elementwise multiply by U: out = rms(in)*sc * U
// ---------------------------------------------------------------------------
__global__ void rms_mul_kernel(const float* __restrict__ in,
                               const float* __restrict__ sc,
                               const float* __restrict__ mul,
                               float* __restrict__ out) {
    int row = blockIdx.x;
    int d = threadIdx.x;
    float v = in[(size_t)row * D_ + d];
    float s = block_sum128(v * v);
    float r = rsqrtf(s * (1.0f / D_) + EPS_);
    out[(size_t)row * D_ + d] = v * r * sc[d] * mul[(size_t)row * D_ + d];
}

// ---------------------------------------------------------------------------
// GEMM: C[M,128] = act(A[M,128] @ W[128,128] + bias) (+ res)
// act: 0 = none, 1 = silu, 2 = exact gelu
// grid = M/64, block = 256. Each thread: 8 rows x 4 cols.
// ---------------------------------------------------------------------------
__global__ void __launch_bounds__(256)
gemm_kernel(const float* __restrict__ A, const float* __restrict__ W,
            const float* __restrict__ bias, const float* __restrict__ res,
            float* __restrict__ C, int act) {
    __shared__ float As[64][32];
    __shared__ float Ws[32][132];

    int tid = threadIdx.x;
    int tm = tid >> 5;        // 0..7   (row group)
    int tn = tid & 31;        // 0..31  (col)
    int row0 = blockIdx.x * 64;

    float acc[8][4];
    #pragma unroll
    for (int i = 0; i < 8; i++)
        #pragma unroll
        for (int j = 0; j < 4; j++) acc[i][j] = 0.0f;

    for (int kk = 0; kk < 128; kk += 32) {
        #pragma unroll
        for (int i = 0; i < 8; i++) {
            int idx = tid + i * 256;          // 0..2047
            int r = idx >> 5, c = idx & 31;
            As[r][c] = A[(size_t)(row0 + r) * 128 + kk + c];
        }
        #pragma unroll
        for (int i = 0; i < 16; i++) {
            int idx = tid + i * 256;          // 0..4095
            int r = idx >> 7, c = idx & 127;
            Ws[r][c] = W[(size_t)(kk + r) * 128 + c];
        }
        __syncthreads();
        #pragma unroll
        for (int k = 0; k < 32; k++) {
            float w0 = Ws[k][tn];
            float w1 = Ws[k][tn + 32];
            float w2 = Ws[k][tn + 64];
            float w3 = Ws[k][tn + 96];
            #pragma unroll
            for (int i = 0; i < 8; i++) {
                float a = As[tm * 8 + i][k];
                acc[i][0] += a * w0;
                acc[i][1] += a * w1;
                acc[i][2] += a * w2;
                acc[i][3] += a * w3;
            }
        }
        __syncthreads();
    }

    #pragma unroll
    for (int i = 0; i < 8; i++) {
        size_t r = (size_t)(row0 + tm * 8 + i);
        #pragma unroll
        for (int j = 0; j < 4; j++) {
            int c = tn + 32 * j;
            float v = acc[i][j] + bias[c];
            if (act == 1) {
                v = v / (1.0f + expf(-v));                       // silu
            } else if (act == 2) {
                v = 0.5f * v * (1.0f + erff(v * 0.70710678118654752f)); // exact gelu
            }
            if (res) v += res[r * 128 + c];
            C[r * 128 + c] = v;
        }
    }
}

// ---------------------------------------------------------------------------
// HSTU attention, single pass (no softmax; sum-normalized silu gates).
// grid = (T_/64, B_*H_), block = 256, dynamic smem.
// Per block: one (b,h) and one 64-row query tile; loops causal key tiles.
// ---------------------------------------------------------------------------
#define QPITCH 65
#define ATTN_SMEM_FLOATS (4 * 64 * QPITCH + 64)
#define ATTN_SMEM_BYTES  (ATTN_SMEM_FLOATS * 4)

__global__ void __launch_bounds__(256)
attn_kernel(const float* __restrict__ Q, const float* __restrict__ K,
            const float* __restrict__ V, float* __restrict__ O) {
    extern __shared__ float sm[];
    float* Qs  = sm;                       // 64 x 65
    float* Ks  = Qs + 64 * QPITCH;         // 64 x 65
    float* Vs  = Ks + 64 * QPITCH;         // 64 x 65
    float* Ss  = Vs + 64 * QPITCH;         // 64 x 65
    float* den = Ss + 64 * QPITCH;         // 64

    int tid = threadIdx.x;
    int qt = blockIdx.x;                   // query tile (0..31)
    int bh = blockIdx.y;                   // b*H + h
    int b = bh >> 1;
    int h = bh & 1;
    int qbase = b * T_ + qt * 64;
    int coloff = h * HD_;

    // load Q tile
    for (int idx = tid; idx < 64 * 64; idx += 256) {
        int r = idx >> 6, c = idx & 63;
        Qs[r * QPITCH + c] = Q[(size_t)(qbase + r) * D_ + coloff + c];
    }
    if (tid < 64) den[tid] = 0.0f;
    __syncthreads();

    int tm = tid >> 4;                     // 0..15 -> 4 query rows each
    int tn = tid & 15;                     // 0..15
    int r0 = tm * 4;
    int j0 = tn * 4;                       // key cols for S compute
    int c0 = tn * 4;                       // value cols for O accumulate

    float o[4][4];
    #pragma unroll
    for (int i = 0; i < 4; i++)
        #pragma unroll
        for (int j = 0; j < 4; j++) o[i][j] = 0.0f;

    const float scale = 0.125f;            // 1/sqrt(64)

    for (int kt = 0; kt <= qt; kt++) {
        int kbase = b * T_ + kt * 64;
        for (int idx = tid; idx < 64 * 64; idx += 256) {
            int r = idx >> 6, c = idx & 63;
            Ks[r * QPITCH + c] = K[(size_t)(kbase + r) * D_ + coloff + c];
            Vs[r * QPITCH + c] = V[(size_t)(kbase + r) * D_ + coloff + c];
        }
        __syncthreads();

        // S = Q @ K^T (4x4 per thread)
        float s[4][4];
        #pragma unroll
        for (int i = 0; i < 4; i++)
            #pragma unroll
            for (int j = 0; j < 4; j++) s[i][j] = 0.0f;

        #pragma unroll 8
        for (int d = 0; d < 64; d++) {
            float q0 = Qs[(r0 + 0) * QPITCH + d];
            float q1 = Qs[(r0 + 1) * QPITCH + d];
            float q2 = Qs[(r0 + 2) * QPITCH + d];
            float q3 = Qs[(r0 + 3) * QPITCH + d];
            float k0 = Ks[(j0 + 0) * QPITCH + d];
            float k1 = Ks[(j0 + 1) * QPITCH + d];
            float k2 = Ks[(j0 + 2) * QPITCH + d];
            float k3 = Ks[(j0 + 3) * QPITCH + d];
            s[0][0] += q0 * k0; s[0][1] += q0 * k1; s[0][2] += q0 * k2; s[0][3] += q0 * k3;
            s[1][0] += q1 * k0; s[1][1] += q1 * k1; s[1][2] += q1 * k2; s[1][3] += q1 * k3;
            s[2][0] += q2 * k0; s[2][1] += q2 * k1; s[2][2] += q2 * k2; s[2][3] += q2 * k3;
            s[3][0] += q3 * k0; s[3][1] += q3 * k1; s[3][2] += q3 * k2; s[3][3] += q3 * k3;
        }

        // gate: max(silu(a),0) with causal mask on the diagonal tile
        bool diag = (kt == qt);
        float rs[4] = {0.f, 0.f, 0.f, 0.f};
        #pragma unroll
        for (int i = 0; i < 4; i++) {
            #pragma unroll
            for (int j = 0; j < 4; j++) {
                float a = s[i][j] * scale;
                float g = 0.0f;
                if (a > 0.0f && (!diag || (j0 + j) <= (r0 + i)))
                    g = a / (1.0f + expf(-a));
                Ss[(r0 + i) * QPITCH + (j0 + j)] = g;
                rs[i] += g;
            }
            atomicAdd(&den[r0 + i], rs[i]);
        }
        __syncthreads();

        // O += S @ V
        #pragma unroll 8
        for (int k = 0; k < 64; k++) {
            float v0 = Vs[k * QPITCH + c0 + 0];
            float v1 = Vs[k * QPITCH + c0 + 1];
            float v2 = Vs[k * QPITCH + c0 + 2];
            float v3 = Vs[k * QPITCH + c0 + 3];
            float s0 = Ss[(r0 + 0) * QPITCH + k];
            float s1 = Ss[(r0 + 1) * QPITCH + k];
            float s2 = Ss[(r0 + 2) * QPITCH + k];
            float s3 = Ss[(r0 + 3) * QPITCH + k];
            o[0][0] += s0 * v0; o[0][1] += s0 * v1; o[0][2] += s0 * v2; o[0][3] += s0 * v3;
            o[1][0] += s1 * v0; o[1][1] += s1 * v1; o[1][2] += s1 * v2; o[1][3] += s1 * v3;
            o[2][0] += s2 * v0; o[2][1] += s2 * v1; o[2][2] += s2 * v2; o[2][3] += s2 * v3;
            o[3][0] += s3 * v0; o[3][1] += s3 * v1; o[3][2] += s3 * v2; o[3][3] += s3 * v3;
        }
        __syncthreads();
    }

    // normalize and write
    #pragma unroll
    for (int i = 0; i < 4; i++) {
        float dd = den[r0 + i];
        float f = (dd > 1e-12f) ? 1.0f / (dd + EPS_) : 0.0f;
        #pragma unroll
        for (int j = 0; j < 4; j++)
            O[(size_t)(qbase + r0 + i) * D_ + coloff + c0 + j] = o[i][j] * f;
    }
}

// ---------------------------------------------------------------------------
// Host orchestration
// ---------------------------------------------------------------------------
extern "C" void kernel_launch(void* const* d_in, const int* in_sizes, int n_in,
                              void* d_out, int out_size) {
    const int*   seq    = (const int*)  d_in[0];
    // d_in[1] = attn_mask (causal tril) — synthesized in-kernel, not read
    const float* item   = (const float*)d_in[2];
    const float* pos    = (const float*)d_in[3];
    const float* emb_s  = (const float*)d_in[4];
    const float* ln1    = (const float*)d_in[5];
    const float* Uw     = (const float*)d_in[6];
    const float* Ub     = (const float*)d_in[7];
    const float* Vw     = (const float*)d_in[8];
    const float* Vb     = (const float*)d_in[9];
    const float* Qw     = (const float*)d_in[10];
    const float* Qb     = (const float*)d_in[11];
    const float* Kw     = (const float*)d_in[12];
    const float* Kb     = (const float*)d_in[13];
    const float* f2w    = (const float*)d_in[14];
    const float* f2b    = (const float*)d_in[15];
    const float* hstu   = (const float*)d_in[16];
    const float* ln2    = (const float*)d_in[17];
    const float* c1w    = (const float*)d_in[18];
    const float* c1b    = (const float*)d_in[19];
    const float* c2w    = (const float*)d_in[20];
    const float* c2b    = (const float*)d_in[21];
    const float* last_s = (const float*)d_in[22];
    float* out = (float*)d_out;

    float *x, *nb, *u, *v, *q, *k, *av, *tb;
    cudaGetSymbolAddress((void**)&x,  g_x);
    cudaGetSymbolAddress((void**)&nb, g_n);
    cudaGetSymbolAddress((void**)&u,  g_u);
    cudaGetSymbolAddress((void**)&v,  g_v);
    cudaGetSymbolAddress((void**)&q,  g_q);
    cudaGetSymbolAddress((void**)&k,  g_k);
    cudaGetSymbolAddress((void**)&av, g_av);
    cudaGetSymbolAddress((void**)&tb, g_t);

    cudaFuncSetAttribute(attn_kernel,
                         cudaFuncAttributeMaxDynamicSharedMemorySize,
                         ATTN_SMEM_BYTES);

    dim3 gemmGrid(BT_ / 64);
    dim3 attnGrid(T_ / 64, B_ * H_);

    embed_rms_kernel<<<BT_, 128>>>(seq, item, pos, emb_s, x);

    for (int l = 0; l < L_; l++) {
        size_t wo = (size_t)l * D_ * D_;
        size_t bo = (size_t)l * D_;

        rms_kernel<<<BT_, 128>>>(x, ln1 + bo, nb);
        gemm_kernel<<<gemmGrid, 256>>>(nb, Uw + wo, Ub + bo, nullptr, u, 1);
        gemm_kernel<<<gemmGrid, 256>>>(nb, Vw + wo, Vb + bo, nullptr, v, 1);
        gemm_kernel<<<gemmGrid, 256>>>(nb, Qw + wo, Qb + bo, nullptr, q, 1);
        gemm_kernel<<<gemmGrid, 256>>>(nb, Kw + wo, Kb + bo, nullptr, k, 1);

        attn_kernel<<<attnGrid, 256, ATTN_SMEM_BYTES>>>(q, k, v, av);

        rms_mul_kernel<<<BT_, 128>>>(av, hstu + bo, u, tb);
        gemm_kernel<<<gemmGrid, 256>>>(tb, f2w + wo, f2b + bo, x, x, 0);

        rms_kernel<<<BT_, 128>>>(x, ln2 + bo, nb);
        gemm_kernel<<<gemmGrid, 256>>>(nb, c1w + wo, c1b + bo, nullptr, tb, 2);
        gemm_kernel<<<gemmGrid, 256>>>(tb, c2w + wo, c2b + bo, x, x, 0);
    }

    rms_kernel<<<BT_, 128>>>(x, last_s, out);
}

// round 2
// speedup vs baseline: 1.2179x; 1.2179x over previous
#include <cuda_runtime.h>
#include <math.h>

// Problem constants
#define B_ 8
#define T_ 2048
#define D_ 128
#define L_ 4
#define H_ 2
#define HD_ 64
#define BT_ (B_ * T_)          // 16384 rows
#define EPS_ 1e-8f

#define GP 132                 // smem pitch (floats) for 128-wide gemm tiles
#define AP 68                  // smem pitch for 64-wide q/k/v tiles
#define SP 132                 // smem pitch for 128-wide S tile

#define GEMM_SMEM ((2 * 128 * GP + 128) * 4)
#define ATTN_SMEM ((3 * 128 * AP + 128 * SP) * 4)

// ---------------------------------------------------------------------------
// Scratch buffers (allocation-free: __device__ globals)
// ---------------------------------------------------------------------------
__device__ float g_x [BT_ * D_];
__device__ float g_u [BT_ * D_];
__device__ float g_v [BT_ * D_];
__device__ float g_q [BT_ * D_];
__device__ float g_k [BT_ * D_];
__device__ float g_av[BT_ * D_];
__device__ float g_t [BT_ * D_];

// ---------------------------------------------------------------------------
// Block-wide sum over 128 threads
// ---------------------------------------------------------------------------
__device__ __forceinline__ float block_sum128(float v) {
    __shared__ float ws[4];
    #pragma unroll
    for (int o = 16; o > 0; o >>= 1) v += __shfl_down_sync(0xffffffffu, v, o);
    if ((threadIdx.x & 31) == 0) ws[threadIdx.x >> 5] = v;
    __syncthreads();
    float s = ws[0] + ws[1] + ws[2] + ws[3];
    __syncthreads();
    return s;
}

// ---------------------------------------------------------------------------
// Embedding gather + positional add + RMSNorm.  grid = BT_, block = 128
// ---------------------------------------------------------------------------
__global__ void embed_rms_kernel(const int* __restrict__ seq,
                                 const float* __restrict__ item,
                                 const float* __restrict__ pos,
                                 const float* __restrict__ sc,
                                 float* __restrict__ out) {
    int row = blockIdx.x;
    int t = row & (T_ - 1);
    int d = threadIdx.x;
    int id = seq[row];
    float v = item[(size_t)id * D_ + d] + pos[(size_t)(t + 1) * D_ + d];
    float s = block_sum128(v * v);
    float r = rsqrtf(s * (1.0f / D_) + EPS_);
    out[(size_t)row * D_ + d] = v * r * sc[d];
}

// ---------------------------------------------------------------------------
// Final RMSNorm.  grid = BT_, block = 128
// ---------------------------------------------------------------------------
__global__ void rms_kernel(const float* __restrict__ in,
                           const float* __restrict__ sc,
                           float* __restrict__ out) {
    int row = blockIdx.x;
    int d = threadIdx.x;
    float v = in[(size_t)row * D_ + d];
    float s = block_sum128(v * v);
    float r = rsqrtf(s * (1.0f / D_) + EPS_);
    out[(size_t)row * D_ + d] = v * r * sc[d];
}

// ---------------------------------------------------------------------------
// Fused GEMM: up to 4 weights against one A tile.
//   A_eff[r][k] = A[r][k] * (use_rms ? rms_r : 1) * (scvec ? scvec[k] : 1)
//                 * (mul ? mul[r][k] : 1)
//   C_w = act(A_eff @ W_w + bias_w) (+ res)
//   rms_r folded into epilogue; scvec folded into Ws at load (both linear).
// grid = 128 blocks (M/128), block = 256, 8x8 outputs per thread.
// ---------------------------------------------------------------------------
__global__ void __launch_bounds__(256)
fused_gemm(const float* __restrict__ A,
           const float* __restrict__ mul,
           const float* __restrict__ scvec,
           int use_rms,
           const float* __restrict__ W0, const float* __restrict__ B0, float* __restrict__ O0,
           const float* __restrict__ W1, const float* __restrict__ B1, float* __restrict__ O1,
           const float* __restrict__ W2, const float* __restrict__ B2, float* __restrict__ O2,
           const float* __restrict__ W3, const float* __restrict__ B3, float* __restrict__ O3,
           const float* __restrict__ res,
           int nw, int act) {
    extern __shared__ float sm[];
    float* As = sm;                 // 128 x GP
    float* Ws = As + 128 * GP;      // 128 x GP
    float* rr = Ws + 128 * GP;      // 128

    int tid = threadIdx.x;
    int row0 = blockIdx.x * 128;

    // load A tile
    for (int idx = tid; idx < 128 * 32; idx += 256) {
        int r = idx >> 5, c4 = (idx & 31) << 2;
        *(float4*)(As + r * GP + c4) =
            *(const float4*)(A + (size_t)(row0 + r) * 128 + c4);
    }
    __syncthreads();

    // row rms (one warp per 16 rows, float4 per lane + shuffle reduce)
    if (use_rms) {
        int w = tid >> 5, lane = tid & 31;
        for (int r = w; r < 128; r += 8) {
            float4 v = *(const float4*)(As + r * GP + lane * 4);
            float ss = v.x * v.x + v.y * v.y + v.z * v.z + v.w * v.w;
            #pragma unroll
            for (int off = 16; off > 0; off >>= 1)
                ss += __shfl_xor_sync(0xffffffffu, ss, off);
            if (lane == 0) rr[r] = rsqrtf(ss * (1.0f / 128.0f) + EPS_);
        }
    } else {
        if (tid < 128) rr[tid] = 1.0f;
    }
    __syncthreads();

    // elementwise multiplier (f2 path: U gate)
    if (mul) {
        for (int idx = tid; idx < 128 * 32; idx += 256) {
            int r = idx >> 5, c4 = (idx & 31) << 2;
            float4 m = *(const float4*)(mul + (size_t)(row0 + r) * 128 + c4);
            float4 a = *(float4*)(As + r * GP + c4);
            a.x *= m.x; a.y *= m.y; a.z *= m.z; a.w *= m.w;
            *(float4*)(As + r * GP + c4) = a;
        }
    }

    int ti = tid >> 4, tj = tid & 15;
    int r0 = ti * 8, c0 = tj * 8;

    const float* Wp[4] = {W0, W1, W2, W3};
    const float* Bp[4] = {B0, B1, B2, B3};
    float*       Op[4] = {O0, O1, O2, O3};

    for (int wi = 0; wi < nw; wi++) {
        const float* W = Wp[wi];
        // load W tile, folding scvec[k] (k = row of W)
        for (int idx = tid; idx < 128 * 32; idx += 256) {
            int r = idx >> 5, c4 = (idx & 31) << 2;
            float s = scvec ? scvec[r] : 1.0f;
            float4 v = *(const float4*)(W + (size_t)r * 128 + c4);
            v.x *= s; v.y *= s; v.z *= s; v.w *= s;
            *(float4*)(Ws + r * GP + c4) = v;
        }
        __syncthreads();

        float acc[8][8];
        #pragma unroll
        for (int i = 0; i < 8; i++)
            #pragma unroll
            for (int j = 0; j < 8; j++) acc[i][j] = 0.0f;

        for (int k = 0; k < 128; k += 4) {
            float4 w0[4], w1[4];
            #pragma unroll
            for (int kk = 0; kk < 4; kk++) {
                w0[kk] = *(const float4*)(Ws + (k + kk) * GP + c0);
                w1[kk] = *(const float4*)(Ws + (k + kk) * GP + c0 + 4);
            }
            #pragma unroll
            for (int i = 0; i < 8; i++) {
                float4 a = *(const float4*)(As + (r0 + i) * GP + k);
                acc[i][0] += a.x * w0[0].x + a.y * w0[1].x + a.z * w0[2].x + a.w * w0[3].x;
                acc[i][1] += a.x * w0[0].y + a.y * w0[1].y + a.z * w0[2].y + a.w * w0[3].y;
                acc[i][2] += a.x * w0[0].z + a.y * w0[1].z + a.z * w0[2].z + a.w * w0[3].z;
                acc[i][3] += a.x * w0[0].w + a.y * w0[1].w + a.z * w0[2].w + a.w * w0[3].w;
                acc[i][4] += a.x * w1[0].x + a.y * w1[1].x + a.z * w1[2].x + a.w * w1[3].x;
                acc[i][5] += a.x * w1[0].y + a.y * w1[1].y + a.z * w1[2].y + a.w * w1[3].y;
                acc[i][6] += a.x * w1[0].z + a.y * w1[1].z + a.z * w1[2].z + a.w * w1[3].z;
                acc[i][7] += a.x * w1[0].w + a.y * w1[1].w + a.z * w1[2].w + a.w * w1[3].w;
            }
        }

        const float* Bv = Bp[wi];
        float* Ov = Op[wi];
        #pragma unroll
        for (int i = 0; i < 8; i++) {
            float rri = rr[r0 + i];
            size_t grow = (size_t)(row0 + r0 + i) * 128;
            float vout[8];
            #pragma unroll
            for (int j = 0; j < 8; j++) {
                float v = acc[i][j] * rri + Bv[c0 + j];
                if (act == 1) {
                    v = v * __fdividef(1.0f, 1.0f + __expf(-v));              // silu
                } else if (act == 2) {
                    v = 0.5f * v * (1.0f + erff(v * 0.70710678118654752f));    // gelu
                }
                vout[j] = v;
            }
            if (res) {
                #pragma unroll
                for (int j = 0; j < 8; j++) vout[j] += res[grow + c0 + j];
            }
            *(float4*)(Ov + grow + c0)     = make_float4(vout[0], vout[1], vout[2], vout[3]);
            *(float4*)(Ov + grow + c0 + 4) = make_float4(vout[4], vout[5], vout[6], vout[7]);
        }
        __syncthreads();
    }
}

// ---------------------------------------------------------------------------
// HSTU attention: 128x128 tiles, 8x8 micro-tile, causal pair load balancing.
// grid = (8, B_*H_), block = 256. Block handles q-tiles qp and 15-qp.
// ---------------------------------------------------------------------------
__global__ void __launch_bounds__(256)
attn_kernel(const float* __restrict__ Q, const float* __restrict__ K,
            const float* __restrict__ V, float* __restrict__ O) {
    extern __shared__ float sm[];
    float* Qs = sm;                  // 128 x AP
    float* Ks = Qs + 128 * AP;
    float* Vs = Ks + 128 * AP;
    float* Ss = Vs + 128 * AP;       // 128 x SP

    int tid = threadIdx.x;
    int ti = tid >> 4, tj = tid & 15;
    int r0 = ti * 8;
    int c0 = tj * 4;                 // output / V columns
    int bh = blockIdx.y;
    int b = bh >> 1, h = bh & 1;
    int coloff = h * HD_;
    int qp = blockIdx.x;

    const float scale = 0.125f;      // 1/sqrt(64)

    for (int half = 0; half < 2; half++) {
        int qt = half ? (15 - qp) : qp;
        int qbase = b * T_ + qt * 128;

        // load Q tile
        for (int idx = tid; idx < 128 * 16; idx += 256) {
            int r = idx >> 4, c4 = (idx & 15) << 2;
            *(float4*)(Qs + r * AP + c4) =
                *(const float4*)(Q + (size_t)(qbase + r) * 128 + coloff + c4);
        }

        float o[8][4];
        float dsum[8];
        #pragma unroll
        for (int i = 0; i < 8; i++) {
            dsum[i] = 0.0f;
            #pragma unroll
            for (int j = 0; j < 4; j++) o[i][j] = 0.0f;
        }

        for (int kt = 0; kt <= qt; kt++) {
            int kbase = b * T_ + kt * 128;
            for (int idx = tid; idx < 128 * 16; idx += 256) {
                int r = idx >> 4, c4 = (idx & 15) << 2;
                *(float4*)(Ks + r * AP + c4) =
                    *(const float4*)(K + (size_t)(kbase + r) * 128 + coloff + c4);
                *(float4*)(Vs + r * AP + c4) =
                    *(const float4*)(V + (size_t)(kbase + r) * 128 + coloff + c4);
            }
            __syncthreads();

            // S = Q @ K^T ; cols j = tj + 16*jj (strided -> 2-way conflicts max)
            float s[8][8];
            #pragma unroll
            for (int i = 0; i < 8; i++)
                #pragma unroll
                for (int j = 0; j < 8; j++) s[i][j] = 0.0f;

            for (int d = 0; d < 64; d += 4) {
                float4 kv[8];
                #pragma unroll
                for (int jj = 0; jj < 8; jj++)
                    kv[jj] = *(const float4*)(Ks + (tj + 16 * jj) * AP + d);
                #pragma unroll
                for (int i = 0; i < 8; i++) {
                    float4 qv = *(const float4*)(Qs + (r0 + i) * AP + d);
                    #pragma unroll
                    for (int jj = 0; jj < 8; jj++)
                        s[i][jj] += qv.x * kv[jj].x + qv.y * kv[jj].y +
                                    qv.z * kv[jj].z + qv.w * kv[jj].w;
                }
            }

            // gate: max(silu(a),0), causal mask on diagonal tile
            bool diag = (kt == qt);
            #pragma unroll
            for (int i = 0; i < 8; i++) {
                int gr = r0 + i;
                #pragma unroll
                for (int jj = 0; jj < 8; jj++) {
                    int col = tj + 16 * jj;
                    float a = s[i][jj] * scale;
                    float g = 0.0f;
                    if (a > 0.0f && (!diag || col <= gr))
                        g = a * __fdividef(1.0f, 1.0f + __expf(-a));
                    Ss[gr * SP + col] = g;
                    dsum[i] += g;
                }
            }
            __syncthreads();

            // O += S @ V
            for (int k = 0; k < 128; k += 4) {
                float4 vv[4];
                #pragma unroll
                for (int kk = 0; kk < 4; kk++)
                    vv[kk] = *(const float4*)(Vs + (k + kk) * AP + c0);
                #pragma unroll
                for (int i = 0; i < 8; i++) {
                    float4 sv = *(const float4*)(Ss + (r0 + i) * SP + k);
                    o[i][0] += sv.x * vv[0].x + sv.y * vv[1].x + sv.z * vv[2].x + sv.w * vv[3].x;
                    o[i][1] += sv.x * vv[0].y + sv.y * vv[1].y + sv.z * vv[2].y + sv.w * vv[3].y;
                    o[i][2] += sv.x * vv[0].z + sv.y * vv[1].z + sv.z * vv[2].z + sv.w * vv[3].z;
                    o[i][3] += sv.x * vv[0].w + sv.y * vv[1].w + sv.z * vv[2].w + sv.w * vv[3].w;
                }
            }
            __syncthreads();
        }

        // row-denominator reduce across the 16 tj lanes, normalize, write
        #pragma unroll
        for (int i = 0; i < 8; i++) {
            float d = dsum[i];
            d += __shfl_xor_sync(0xffffffffu, d, 1);
            d += __shfl_xor_sync(0xffffffffu, d, 2);
            d += __shfl_xor_sync(0xffffffffu, d, 4);
            d += __shfl_xor_sync(0xffffffffu, d, 8);
            float f = (d > 1e-12f) ? __fdividef(1.0f, d + EPS_) : 0.0f;
            *(float4*)(O + (size_t)(qbase + r0 + i) * 128 + coloff + c0) =
                make_float4(o[i][0] * f, o[i][1] * f, o[i][2] * f, o[i][3] * f);
        }
        __syncthreads();
    }
}

// ---------------------------------------------------------------------------
// Host orchestration
// ---------------------------------------------------------------------------
extern "C" void kernel_launch(void* const* d_in, const int* in_sizes, int n_in,
                              void* d_out, int out_size) {
    const int*   seq    = (const int*)  d_in[0];
    // d_in[1] = attn_mask (causal tril) — synthesized in-kernel
    const float* item   = (const float*)d_in[2];
    const float* pos    = (const float*)d_in[3];
    const float* emb_s  = (const float*)d_in[4];
    const float* ln1    = (const float*)d_in[5];
    const float* Uw     = (const float*)d_in[6];
    const float* Ub     = (const float*)d_in[7];
    const float* Vw     = (const float*)d_in[8];
    const float* Vb     = (const float*)d_in[9];
    const float* Qw     = (const float*)d_in[10];
    const float* Qb     = (const float*)d_in[11];
    const float* Kw     = (const float*)d_in[12];
    const float* Kb     = (const float*)d_in[13];
    const float* f2w    = (const float*)d_in[14];
    const float* f2b    = (const float*)d_in[15];
    const float* hstu   = (const float*)d_in[16];
    const float* ln2    = (const float*)d_in[17];
    const float* c1w    = (const float*)d_in[18];
    const float* c1b    = (const float*)d_in[19];
    const float* c2w    = (const float*)d_in[20];
    const float* c2b    = (const float*)d_in[21];
    const float* last_s = (const float*)d_in[22];
    float* out = (float*)d_out;

    float *x, *u, *v, *q, *k, *av, *tb;
    cudaGetSymbolAddress((void**)&x,  g_x);
    cudaGetSymbolAddress((void**)&u,  g_u);
    cudaGetSymbolAddress((void**)&v,  g_v);
    cudaGetSymbolAddress((void**)&q,  g_q);
    cudaGetSymbolAddress((void**)&k,  g_k);
    cudaGetSymbolAddress((void**)&av, g_av);
    cudaGetSymbolAddress((void**)&tb, g_t);

    cudaFuncSetAttribute(fused_gemm,
                         cudaFuncAttributeMaxDynamicSharedMemorySize, GEMM_SMEM);
    cudaFuncSetAttribute(attn_kernel,
                         cudaFuncAttributeMaxDynamicSharedMemorySize, ATTN_SMEM);

    dim3 gemmGrid(BT_ / 128);
    dim3 attnGrid(8, B_ * H_);

    embed_rms_kernel<<<BT_, 128>>>(seq, item, pos, emb_s, x);

    for (int l = 0; l < L_; l++) {
        size_t wo = (size_t)l * D_ * D_;
        size_t bo = (size_t)l * D_;

        // QKVU: rms(x)*ln1 folded in; silu epilogue; 4 outputs
        fused_gemm<<<gemmGrid, 256, GEMM_SMEM>>>(
            x, nullptr, ln1 + bo, 1,
            Uw + wo, Ub + bo, u,
            Vw + wo, Vb + bo, v,
            Qw + wo, Qb + bo, q,
            Kw + wo, Kb + bo, k,
            nullptr, 4, 1);

        attn_kernel<<<attnGrid, 256, ATTN_SMEM>>>(q, k, v, av);

        // x += (rms(av)*hstu_s * u) @ f2w + f2b
        fused_gemm<<<gemmGrid, 256, GEMM_SMEM>>>(
            av, u, hstu + bo, 1,
            f2w + wo, f2b + bo, x,
            nullptr, nullptr, nullptr,
            nullptr, nullptr, nullptr,
            nullptr, nullptr, nullptr,
            x, 1, 0);

        // h = gelu(rms(x)*ln2 @ c1w + c1b)
        fused_gemm<<<gemmGrid, 256, GEMM_SMEM>>>(
            x, nullptr, ln2 + bo, 1,
            c1w + wo, c1b + bo, tb,
            nullptr, nullptr, nullptr,
            nullptr, nullptr, nullptr,
            nullptr, nullptr, nullptr,
            nullptr, 1, 2);

        // x += h @ c2w + c2b
        fused_gemm<<<gemmGrid, 256, GEMM_SMEM>>>(
            tb, nullptr, nullptr, 0,
            c2w + wo, c2b + bo, x,
            nullptr, nullptr, nullptr,
            nullptr, nullptr, nullptr,
            nullptr, nullptr, nullptr,
            x, 1, 0);
    }

    rms_kernel<<<BT_, 128>>>(x, last_s, out);
}

// round 3
// speedup vs baseline: 1.2646x; 1.0384x over previous
#include <cuda_runtime.h>
#include <math.h>

// Problem constants
#define B_ 8
#define T_ 2048
#define D_ 128
#define L_ 4
#define H_ 2
#define HD_ 64
#define BT_ (B_ * T_)          // 16384 rows
#define EPS_ 1e-8f

#define GP 132                 // smem pitch (floats) for 128-wide gemm tiles
#define AP 68                  // smem pitch for 64-wide q/k/v tiles
#define SP 132                 // smem pitch for 128-wide S tile

#define GEMM_SMEM ((2 * 128 * GP + 128) * 4)
#define ATTN_SMEM ((3 * 128 * AP + 128 * SP) * 4)

// ---------------------------------------------------------------------------
// Scratch buffers (allocation-free: __device__ globals)
// ---------------------------------------------------------------------------
__device__ float g_x [BT_ * D_];
__device__ float g_u [BT_ * D_];
__device__ float g_v [BT_ * D_];
__device__ float g_q [BT_ * D_];
__device__ float g_k [BT_ * D_];
__device__ float g_av[BT_ * D_];
__device__ float g_t [BT_ * D_];

// ---------------------------------------------------------------------------
// Warp-per-row RMSNorm helpers (memory-bound elementwise kernels)
// grid = BT_/8, block = 256 (8 warps = 8 rows)
// ---------------------------------------------------------------------------
__global__ void rms_kernel(const float* __restrict__ in,
                           const float* __restrict__ sc,
                           float* __restrict__ out) {
    int warp = threadIdx.x >> 5, lane = threadIdx.x & 31;
    size_t row = (size_t)blockIdx.x * 8 + warp;
    float4 v = *(const float4*)(in + row * 128 + lane * 4);
    float ss = v.x * v.x + v.y * v.y + v.z * v.z + v.w * v.w;
    #pragma unroll
    for (int o = 16; o > 0; o >>= 1) ss += __shfl_xor_sync(0xffffffffu, ss, o);
    float r = rsqrtf(ss * (1.0f / 128.0f) + EPS_);
    float4 s = *(const float4*)(sc + lane * 4);
    *(float4*)(out + row * 128 + lane * 4) =
        make_float4(v.x * r * s.x, v.y * r * s.y, v.z * r * s.z, v.w * r * s.w);
}

__global__ void embed_rms_kernel(const int* __restrict__ seq,
                                 const float* __restrict__ item,
                                 const float* __restrict__ pos,
                                 const float* __restrict__ sc,
                                 float* __restrict__ out) {
    int warp = threadIdx.x >> 5, lane = threadIdx.x & 31;
    size_t row = (size_t)blockIdx.x * 8 + warp;
    int t = (int)(row & (T_ - 1));
    int id = seq[row];
    float4 a = *(const float4*)(item + (size_t)id * 128 + lane * 4);
    float4 p = *(const float4*)(pos + (size_t)(t + 1) * 128 + lane * 4);
    float4 v = make_float4(a.x + p.x, a.y + p.y, a.z + p.z, a.w + p.w);
    float ss = v.x * v.x + v.y * v.y + v.z * v.z + v.w * v.w;
    #pragma unroll
    for (int o = 16; o > 0; o >>= 1) ss += __shfl_xor_sync(0xffffffffu, ss, o);
    float r = rsqrtf(ss * (1.0f / 128.0f) + EPS_);
    float4 s = *(const float4*)(sc + lane * 4);
    *(float4*)(out + row * 128 + lane * 4) =
        make_float4(v.x * r * s.x, v.y * r * s.y, v.z * r * s.z, v.w * r * s.w);
}

// ---------------------------------------------------------------------------
// Fused GEMM: up to 4 weights against one A tile.
//   A_eff[r][k] = A[r][k] * (use_rms ? rms_r : 1) * (scvec ? scvec[k] : 1)
//                 * (mul ? mul[r][k] : 1)
//   C_w = act(A_eff @ W_w + bias_w) (+ res)
// grid = 128 blocks (M/128), block = 512, 4x8 outputs per thread.
// ---------------------------------------------------------------------------
__global__ void __launch_bounds__(512)
fused_gemm(const float* __restrict__ A,
           const float* __restrict__ mul,
           const float* __restrict__ scvec,
           int use_rms,
           const float* __restrict__ W0, const float* __restrict__ B0, float* __restrict__ O0,
           const float* __restrict__ W1, const float* __restrict__ B1, float* __restrict__ O1,
           const float* __restrict__ W2, const float* __restrict__ B2, float* __restrict__ O2,
           const float* __restrict__ W3, const float* __restrict__ B3, float* __restrict__ O3,
           const float* __restrict__ res,
           int nw, int act) {
    extern __shared__ float sm[];
    float* As = sm;                 // 128 x GP
    float* Ws = As + 128 * GP;      // 128 x GP
    float* rr = Ws + 128 * GP;      // 128

    int tid = threadIdx.x;
    int row0 = blockIdx.x * 128;

    // load A tile (4096 float4 over 512 threads)
    for (int idx = tid; idx < 128 * 32; idx += 512) {
        int r = idx >> 5, c4 = (idx & 31) << 2;
        *(float4*)(As + r * GP + c4) =
            *(const float4*)(A + (size_t)(row0 + r) * 128 + c4);
    }
    __syncthreads();

    // row rms (warp per row, 16 warps)
    if (use_rms) {
        int w = tid >> 5, lane = tid & 31;
        for (int r = w; r < 128; r += 16) {
            float4 v = *(const float4*)(As + r * GP + lane * 4);
            float ss = v.x * v.x + v.y * v.y + v.z * v.z + v.w * v.w;
            #pragma unroll
            for (int off = 16; off > 0; off >>= 1)
                ss += __shfl_xor_sync(0xffffffffu, ss, off);
            if (lane == 0) rr[r] = rsqrtf(ss * (1.0f / 128.0f) + EPS_);
        }
    } else {
        if (tid < 128) rr[tid] = 1.0f;
    }
    __syncthreads();

    // elementwise multiplier (f2 path: U gate)
    if (mul) {
        for (int idx = tid; idx < 128 * 32; idx += 512) {
            int r = idx >> 5, c4 = (idx & 31) << 2;
            float4 m = *(const float4*)(mul + (size_t)(row0 + r) * 128 + c4);
            float4 a = *(float4*)(As + r * GP + c4);
            a.x *= m.x; a.y *= m.y; a.z *= m.z; a.w *= m.w;
            *(float4*)(As + r * GP + c4) = a;
        }
    }

    int ti = tid >> 4, tj = tid & 15;      // ti: 0..31, tj: 0..15
    int r0 = ti * 4, c0 = tj * 8;

    const float* Wp[4] = {W0, W1, W2, W3};
    const float* Bp[4] = {B0, B1, B2, B3};
    float*       Op[4] = {O0, O1, O2, O3};

    for (int wi = 0; wi < nw; wi++) {
        const float* W = Wp[wi];
        // load W tile, folding scvec[k] (k = row of W)
        for (int idx = tid; idx < 128 * 32; idx += 512) {
            int r = idx >> 5, c4 = (idx & 31) << 2;
            float s = scvec ? scvec[r] : 1.0f;
            float4 v = *(const float4*)(W + (size_t)r * 128 + c4);
            v.x *= s; v.y *= s; v.z *= s; v.w *= s;
            *(float4*)(Ws + r * GP + c4) = v;
        }
        __syncthreads();

        float acc[4][8];
        #pragma unroll
        for (int i = 0; i < 4; i++)
            #pragma unroll
            for (int j = 0; j < 8; j++) acc[i][j] = 0.0f;

        for (int k = 0; k < 128; k += 4) {
            float4 w0[4], w1[4];
            #pragma unroll
            for (int kk = 0; kk < 4; kk++) {
                w0[kk] = *(const float4*)(Ws + (k + kk) * GP + c0);
                w1[kk] = *(const float4*)(Ws + (k + kk) * GP + c0 + 4);
            }
            #pragma unroll
            for (int i = 0; i < 4; i++) {
                float4 a = *(const float4*)(As + (r0 + i) * GP + k);
                acc[i][0] += a.x * w0[0].x + a.y * w0[1].x + a.z * w0[2].x + a.w * w0[3].x;
                acc[i][1] += a.x * w0[0].y + a.y * w0[1].y + a.z * w0[2].y + a.w * w0[3].y;
                acc[i][2] += a.x * w0[0].z + a.y * w0[1].z + a.z * w0[2].z + a.w * w0[3].z;
                acc[i][3] += a.x * w0[0].w + a.y * w0[1].w + a.z * w0[2].w + a.w * w0[3].w;
                acc[i][4] += a.x * w1[0].x + a.y * w1[1].x + a.z * w1[2].x + a.w * w1[3].x;
                acc[i][5] += a.x * w1[0].y + a.y * w1[1].y + a.z * w1[2].y + a.w * w1[3].y;
                acc[i][6] += a.x * w1[0].z + a.y * w1[1].z + a.z * w1[2].z + a.w * w1[3].z;
                acc[i][7] += a.x * w1[0].w + a.y * w1[1].w + a.z * w1[2].w + a.w * w1[3].w;
            }
        }

        const float* Bv = Bp[wi];
        float* Ov = Op[wi];
        #pragma unroll
        for (int i = 0; i < 4; i++) {
            float rri = rr[r0 + i];
            size_t grow = (size_t)(row0 + r0 + i) * 128;
            float vout[8];
            #pragma unroll
            for (int j = 0; j < 8; j++) {
                float v = acc[i][j] * rri + Bv[c0 + j];
                if (act == 1) {
                    v = v * __fdividef(1.0f, 1.0f + __expf(-v));               // silu
                } else if (act == 2) {
                    v = 0.5f * v * (1.0f + erff(v * 0.70710678118654752f));    // gelu
                }
                vout[j] = v;
            }
            if (res) {
                #pragma unroll
                for (int j = 0; j < 8; j++) vout[j] += res[grow + c0 + j];
            }
            *(float4*)(Ov + grow + c0)     = make_float4(vout[0], vout[1], vout[2], vout[3]);
            *(float4*)(Ov + grow + c0 + 4) = make_float4(vout[4], vout[5], vout[6], vout[7]);
        }
        __syncthreads();
    }
}

// ---------------------------------------------------------------------------
// HSTU attention: 128x128 tiles, causal pair load balancing.
// grid = (8, B_*H_), block = 512. Block handles q-tiles qp and 15-qp.
// Thread micro-tile: S = 4x8 (cols strided by 16), O = 4x4.
// ---------------------------------------------------------------------------
__global__ void __launch_bounds__(512)
attn_kernel(const float* __restrict__ Q, const float* __restrict__ K,
            const float* __restrict__ V, float* __restrict__ O) {
    extern __shared__ float sm[];
    float* Qs = sm;                  // 128 x AP
    float* Ks = Qs + 128 * AP;
    float* Vs = Ks + 128 * AP;
    float* Ss = Vs + 128 * AP;       // 128 x SP

    int tid = threadIdx.x;
    int ti = tid >> 4, tj = tid & 15;   // ti: 0..31, tj: 0..15
    int r0 = ti * 4;
    int c0 = tj * 4;                    // output / V columns (64 wide)
    int bh = blockIdx.y;
    int b = bh >> 1, h = bh & 1;
    int coloff = h * HD_;
    int qp = blockIdx.x;

    const float scale = 0.125f;         // 1/sqrt(64)

    for (int half = 0; half < 2; half++) {
        int qt = half ? (15 - qp) : qp;
        int qbase = b * T_ + qt * 128;

        // load Q tile (2048 float4 over 512 threads)
        for (int idx = tid; idx < 128 * 16; idx += 512) {
            int r = idx >> 4, c4 = (idx & 15) << 2;
            *(float4*)(Qs + r * AP + c4) =
                *(const float4*)(Q + (size_t)(qbase + r) * 128 + coloff + c4);
        }

        float o[4][4];
        float dsum[4];
        #pragma unroll
        for (int i = 0; i < 4; i++) {
            dsum[i] = 0.0f;
            #pragma unroll
            for (int j = 0; j < 4; j++) o[i][j] = 0.0f;
        }

        for (int kt = 0; kt <= qt; kt++) {
            int kbase = b * T_ + kt * 128;
            for (int idx = tid; idx < 128 * 16; idx += 512) {
                int r = idx >> 4, c4 = (idx & 15) << 2;
                *(float4*)(Ks + r * AP + c4) =
                    *(const float4*)(K + (size_t)(kbase + r) * 128 + coloff + c4);
                *(float4*)(Vs + r * AP + c4) =
                    *(const float4*)(V + (size_t)(kbase + r) * 128 + coloff + c4);
            }
            __syncthreads();

            // S = Q @ K^T ; cols j = tj + 16*jj
            float s[4][8];
            #pragma unroll
            for (int i = 0; i < 4; i++)
                #pragma unroll
                for (int j = 0; j < 8; j++) s[i][j] = 0.0f;

            for (int d = 0; d < 64; d += 4) {
                float4 kv[8];
                #pragma unroll
                for (int jj = 0; jj < 8; jj++)
                    kv[jj] = *(const float4*)(Ks + (tj + 16 * jj) * AP + d);
                #pragma unroll
                for (int i = 0; i < 4; i++) {
                    float4 qv = *(const float4*)(Qs + (r0 + i) * AP + d);
                    #pragma unroll
                    for (int jj = 0; jj < 8; jj++)
                        s[i][jj] += qv.x * kv[jj].x + qv.y * kv[jj].y +
                                    qv.z * kv[jj].z + qv.w * kv[jj].w;
                }
            }

            // gate: max(silu(a),0), causal mask on diagonal tile
            bool diag = (kt == qt);
            #pragma unroll
            for (int i = 0; i < 4; i++) {
                int gr = r0 + i;
                #pragma unroll
                for (int jj = 0; jj < 8; jj++) {
                    int col = tj + 16 * jj;
                    float a = s[i][jj] * scale;
                    float g = 0.0f;
                    if (a > 0.0f && (!diag || col <= gr))
                        g = a * __fdividef(1.0f, 1.0f + __expf(-a));
                    Ss[gr * SP + col] = g;
                    dsum[i] += g;
                }
            }
            __syncthreads();

            // O += S @ V
            for (int k = 0; k < 128; k += 4) {
                float4 vv[4];
                #pragma unroll
                for (int kk = 0; kk < 4; kk++)
                    vv[kk] = *(const float4*)(Vs + (k + kk) * AP + c0);
                #pragma unroll
                for (int i = 0; i < 4; i++) {
                    float4 sv = *(const float4*)(Ss + (r0 + i) * SP + k);
                    o[i][0] += sv.x * vv[0].x + sv.y * vv[1].x + sv.z * vv[2].x + sv.w * vv[3].x;
                    o[i][1] += sv.x * vv[0].y + sv.y * vv[1].y + sv.z * vv[2].y + sv.w * vv[3].y;
                    o[i][2] += sv.x * vv[0].z + sv.y * vv[1].z + sv.z * vv[2].z + sv.w * vv[3].z;
                    o[i][3] += sv.x * vv[0].w + sv.y * vv[1].w + sv.z * vv[2].w + sv.w * vv[3].w;
                }
            }
            __syncthreads();
        }

        // row-denominator reduce across 16 tj lanes, normalize, write
        #pragma unroll
        for (int i = 0; i < 4; i++) {
            float d = dsum[i];
            d += __shfl_xor_sync(0xffffffffu, d, 1);
            d += __shfl_xor_sync(0xffffffffu, d, 2);
            d += __shfl_xor_sync(0xffffffffu, d, 4);
            d += __shfl_xor_sync(0xffffffffu, d, 8);
            float f = (d > 1e-12f) ? __fdividef(1.0f, d + EPS_) : 0.0f;
            *(float4*)(O + (size_t)(qbase + r0 + i) * 128 + coloff + c0) =
                make_float4(o[i][0] * f, o[i][1] * f, o[i][2] * f, o[i][3] * f);
        }
        __syncthreads();
    }
}

// ---------------------------------------------------------------------------
// Host orchestration
// ---------------------------------------------------------------------------
extern "C" void kernel_launch(void* const* d_in, const int* in_sizes, int n_in,
                              void* d_out, int out_size) {
    const int*   seq    = (const int*)  d_in[0];
    // d_in[1] = attn_mask (causal tril) — synthesized in-kernel
    const float* item   = (const float*)d_in[2];
    const float* pos    = (const float*)d_in[3];
    const float* emb_s  = (const float*)d_in[4];
    const float* ln1    = (const float*)d_in[5];
    const float* Uw     = (const float*)d_in[6];
    const float* Ub     = (const float*)d_in[7];
    const float* Vw     = (const float*)d_in[8];
    const float* Vb     = (const float*)d_in[9];
    const float* Qw     = (const float*)d_in[10];
    const float* Qb     = (const float*)d_in[11];
    const float* Kw     = (const float*)d_in[12];
    const float* Kb     = (const float*)d_in[13];
    const float* f2w    = (const float*)d_in[14];
    const float* f2b    = (const float*)d_in[15];
    const float* hstu   = (const float*)d_in[16];
    const float* ln2    = (const float*)d_in[17];
    const float* c1w    = (const float*)d_in[18];
    const float* c1b    = (const float*)d_in[19];
    const float* c2w    = (const float*)d_in[20];
    const float* c2b    = (const float*)d_in[21];
    const float* last_s = (const float*)d_in[22];
    float* out = (float*)d_out;

    float *x, *u, *v, *q, *k, *av, *tb;
    cudaGetSymbolAddress((void**)&x,  g_x);
    cudaGetSymbolAddress((void**)&u,  g_u);
    cudaGetSymbolAddress((void**)&v,  g_v);
    cudaGetSymbolAddress((void**)&q,  g_q);
    cudaGetSymbolAddress((void**)&k,  g_k);
    cudaGetSymbolAddress((void**)&av, g_av);
    cudaGetSymbolAddress((void**)&tb, g_t);

    cudaFuncSetAttribute(fused_gemm,
                         cudaFuncAttributeMaxDynamicSharedMemorySize, GEMM_SMEM);
    cudaFuncSetAttribute(attn_kernel,
                         cudaFuncAttributeMaxDynamicSharedMemorySize, ATTN_SMEM);

    dim3 gemmGrid(BT_ / 128);
    dim3 attnGrid(8, B_ * H_);

    embed_rms_kernel<<<BT_ / 8, 256>>>(seq, item, pos, emb_s, x);

    for (int l = 0; l < L_; l++) {
        size_t wo = (size_t)l * D_ * D_;
        size_t bo = (size_t)l * D_;

        // QKVU: rms(x)*ln1 folded in; silu epilogue; 4 outputs
        fused_gemm<<<gemmGrid, 512, GEMM_SMEM>>>(
            x, nullptr, ln1 + bo, 1,
            Uw + wo, Ub + bo, u,
            Vw + wo, Vb + bo, v,
            Qw + wo, Qb + bo, q,
            Kw + wo, Kb + bo, k,
            nullptr, 4, 1);

        attn_kernel<<<attnGrid, 512, ATTN_SMEM>>>(q, k, v, av);

        // x += (rms(av)*hstu_s * u) @ f2w + f2b
        fused_gemm<<<gemmGrid, 512, GEMM_SMEM>>>(
            av, u, hstu + bo, 1,
            f2w + wo, f2b + bo, x,
            nullptr, nullptr, nullptr,
            nullptr, nullptr, nullptr,
            nullptr, nullptr, nullptr,
            x, 1, 0);

        // h = gelu(rms(x)*ln2 @ c1w + c1b)
        fused_gemm<<<gemmGrid, 512, GEMM_SMEM>>>(
            x, nullptr, ln2 + bo, 1,
            c1w + wo, c1b + bo, tb,
            nullptr, nullptr, nullptr,
            nullptr, nullptr, nullptr,
            nullptr, nullptr, nullptr,
            nullptr, 1, 2);

        // x += h @ c2w + c2b
        fused_gemm<<<gemmGrid, 512, GEMM_SMEM>>>(
            tb, nullptr, nullptr, 0,
            c2w + wo, c2b + bo, x,
            nullptr, nullptr, nullptr,
            nullptr, nullptr, nullptr,
            nullptr, nullptr, nullptr,
            x, 1, 0);
    }

    rms_kernel<<<BT_ / 8, 256>>>(x, last_s, out);
}

// round 6
// speedup vs baseline: 1.8361x; 1.4519x over previous
#include <cuda_runtime.h>
#include <cuda_bf16.h>
#include <math.h>
#include <stdint.h>

// Problem constants
#define B_ 8
#define T_ 2048
#define D_ 128
#define L_ 4
#define H_ 2
#define HD_ 64
#define BT_ (B_ * T_)          // 16384 rows
#define EPS_ 1e-8f

#define GP 132                 // smem pitch (floats) for 128-wide gemm tiles
#define GEMM_SMEM ((2 * 128 * GP + 128) * 4)

// ---------------------------------------------------------------------------
// Scratch buffers (allocation-free: __device__ globals)
// ---------------------------------------------------------------------------
__device__ float g_x [BT_ * D_];
__device__ float g_u [BT_ * D_];
__device__ float g_v [BT_ * D_];
__device__ float g_q [BT_ * D_];
__device__ float g_k [BT_ * D_];
__device__ float g_av[BT_ * D_];
__device__ float g_t [BT_ * D_];

// ===========================================================================
// Small helpers
// ===========================================================================
__device__ __forceinline__ uint32_t smem_u32(const void* p) {
    uint32_t a;
    asm("{ .reg .u64 t; cvta.to.shared.u64 t, %1; cvt.u32.u64 %0, t; }"
        : "=r"(a) : "l"(p));
    return a;
}

// bf16 hi/lo split of an fp32 value
__device__ __forceinline__ void split_bf16(float x, unsigned short& h, unsigned short& l) {
    __nv_bfloat16 hb = __float2bfloat16(x);
    float hf = __bfloat162float(hb);
    __nv_bfloat16 lb = __float2bfloat16(x - hf);
    h = __bfloat16_as_ushort(hb);
    l = __bfloat16_as_ushort(lb);
}

__device__ __forceinline__ uint32_t bf16x2_hi(float x, float y) {
    __nv_bfloat162 t = __floats2bfloat162_rn(x, y);  // .x = x in low half
    return *reinterpret_cast<uint32_t*>(&t);
}
__device__ __forceinline__ uint32_t bf16x2_lo(float x, float y) {
    float xh = __bfloat162float(__float2bfloat16(x));
    float yh = __bfloat162float(__float2bfloat16(y));
    __nv_bfloat162 t = __floats2bfloat162_rn(x - xh, y - yh);
    return *reinterpret_cast<uint32_t*>(&t);
}

// mma.sync m16n8k16 bf16 -> f32 (accumulate in place)
__device__ __forceinline__ void mma16816(float* c, const uint32_t* a,
                                         uint32_t b0, uint32_t b1) {
    asm volatile(
        "mma.sync.aligned.m16n8k16.row.col.f32.bf16.bf16.f32 "
        "{%0,%1,%2,%3}, {%4,%5,%6,%7}, {%8,%9}, {%0,%1,%2,%3};"
        : "+f"(c[0]), "+f"(c[1]), "+f"(c[2]), "+f"(c[3])
        : "r"(a[0]), "r"(a[1]), "r"(a[2]), "r"(a[3]), "r"(b0), "r"(b1));
}

// ldmatrix x2 transposed (for V B-fragments from row-major V[key][d])
__device__ __forceinline__ void ldsm_x2_trans(uint32_t& r0, uint32_t& r1, uint32_t addr) {
    asm volatile("ldmatrix.sync.aligned.m8n8.x2.trans.shared.b16 {%0,%1}, [%2];"
                 : "=r"(r0), "=r"(r1) : "r"(addr));
}

// ===========================================================================
// Elementwise RMS kernels
// ===========================================================================
__global__ void rms_kernel(const float* __restrict__ in,
                           const float* __restrict__ sc,
                           float* __restrict__ out) {
    int warp = threadIdx.x >> 5, lane = threadIdx.x & 31;
    size_t row = (size_t)blockIdx.x * 8 + warp;
    float4 v = *(const float4*)(in + row * 128 + lane * 4);
    float ss = v.x * v.x + v.y * v.y + v.z * v.z + v.w * v.w;
    #pragma unroll
    for (int o = 16; o > 0; o >>= 1) ss += __shfl_xor_sync(0xffffffffu, ss, o);
    float r = rsqrtf(ss * (1.0f / 128.0f) + EPS_);
    float4 s = *(const float4*)(sc + lane * 4);
    *(float4*)(out + row * 128 + lane * 4) =
        make_float4(v.x * r * s.x, v.y * r * s.y, v.z * r * s.z, v.w * r * s.w);
}

__global__ void embed_rms_kernel(const int* __restrict__ seq,
                                 const float* __restrict__ item,
                                 const float* __restrict__ pos,
                                 const float* __restrict__ sc,
                                 float* __restrict__ out) {
    int warp = threadIdx.x >> 5, lane = threadIdx.x & 31;
    size_t row = (size_t)blockIdx.x * 8 + warp;
    int t = (int)(row & (T_ - 1));
    int id = seq[row];
    float4 a = *(const float4*)(item + (size_t)id * 128 + lane * 4);
    float4 p = *(const float4*)(pos + (size_t)(t + 1) * 128 + lane * 4);
    float4 v = make_float4(a.x + p.x, a.y + p.y, a.z + p.z, a.w + p.w);
    float ss = v.x * v.x + v.y * v.y + v.z * v.z + v.w * v.w;
    #pragma unroll
    for (int o = 16; o > 0; o >>= 1) ss += __shfl_xor_sync(0xffffffffu, ss, o);
    float r = rsqrtf(ss * (1.0f / 128.0f) + EPS_);
    float4 s = *(const float4*)(sc + lane * 4);
    *(float4*)(out + row * 128 + lane * 4) =
        make_float4(v.x * r * s.x, v.y * r * s.y, v.z * r * s.z, v.w * r * s.w);
}

// ===========================================================================
// Fused GEMM (fp32 SIMT, known good)
// ===========================================================================
__global__ void __launch_bounds__(512)
fused_gemm(const float* __restrict__ A,
           const float* __restrict__ mul,
           const float* __restrict__ scvec,
           int use_rms,
           const float* __restrict__ W0, const float* __restrict__ B0, float* __restrict__ O0,
           const float* __restrict__ W1, const float* __restrict__ B1, float* __restrict__ O1,
           const float* __restrict__ W2, const float* __restrict__ B2, float* __restrict__ O2,
           const float* __restrict__ W3, const float* __restrict__ B3, float* __restrict__ O3,
           const float* __restrict__ res,
           int nw, int act) {
    extern __shared__ float sm[];
    float* As = sm;
    float* Ws = As + 128 * GP;
    float* rr = Ws + 128 * GP;

    int tid = threadIdx.x;
    int row0 = blockIdx.x * 128;

    for (int idx = tid; idx < 128 * 32; idx += 512) {
        int r = idx >> 5, c4 = (idx & 31) << 2;
        *(float4*)(As + r * GP + c4) =
            *(const float4*)(A + (size_t)(row0 + r) * 128 + c4);
    }
    __syncthreads();

    if (use_rms) {
        int w = tid >> 5, lane = tid & 31;
        for (int r = w; r < 128; r += 16) {
            float4 v = *(const float4*)(As + r * GP + lane * 4);
            float ss = v.x * v.x + v.y * v.y + v.z * v.z + v.w * v.w;
            #pragma unroll
            for (int off = 16; off > 0; off >>= 1)
                ss += __shfl_xor_sync(0xffffffffu, ss, off);
            if (lane == 0) rr[r] = rsqrtf(ss * (1.0f / 128.0f) + EPS_);
        }
    } else {
        if (tid < 128) rr[tid] = 1.0f;
    }
    __syncthreads();

    if (mul) {
        for (int idx = tid; idx < 128 * 32; idx += 512) {
            int r = idx >> 5, c4 = (idx & 31) << 2;
            float4 m = *(const float4*)(mul + (size_t)(row0 + r) * 128 + c4);
            float4 a = *(float4*)(As + r * GP + c4);
            a.x *= m.x; a.y *= m.y; a.z *= m.z; a.w *= m.w;
            *(float4*)(As + r * GP + c4) = a;
        }
    }

    int ti = tid >> 4, tj = tid & 15;
    int r0 = ti * 4, c0 = tj * 8;

    const float* Wp[4] = {W0, W1, W2, W3};
    const float* Bp[4] = {B0, B1, B2, B3};
    float*       Op[4] = {O0, O1, O2, O3};

    for (int wi = 0; wi < nw; wi++) {
        const float* W = Wp[wi];
        for (int idx = tid; idx < 128 * 32; idx += 512) {
            int r = idx >> 5, c4 = (idx & 31) << 2;
            float s = scvec ? scvec[r] : 1.0f;
            float4 v = *(const float4*)(W + (size_t)r * 128 + c4);
            v.x *= s; v.y *= s; v.z *= s; v.w *= s;
            *(float4*)(Ws + r * GP + c4) = v;
        }
        __syncthreads();

        float acc[4][8];
        #pragma unroll
        for (int i = 0; i < 4; i++)
            #pragma unroll
            for (int j = 0; j < 8; j++) acc[i][j] = 0.0f;

        for (int k = 0; k < 128; k += 4) {
            float4 w0[4], w1[4];
            #pragma unroll
            for (int kk = 0; kk < 4; kk++) {
                w0[kk] = *(const float4*)(Ws + (k + kk) * GP + c0);
                w1[kk] = *(const float4*)(Ws + (k + kk) * GP + c0 + 4);
            }
            #pragma unroll
            for (int i = 0; i < 4; i++) {
                float4 a = *(const float4*)(As + (r0 + i) * GP + k);
                acc[i][0] += a.x * w0[0].x + a.y * w0[1].x + a.z * w0[2].x + a.w * w0[3].x;
                acc[i][1] += a.x * w0[0].y + a.y * w0[1].y + a.z * w0[2].y + a.w * w0[3].y;
                acc[i][2] += a.x * w0[0].z + a.y * w0[1].z + a.z * w0[2].z + a.w * w0[3].z;
                acc[i][3] += a.x * w0[0].w + a.y * w0[1].w + a.z * w0[2].w + a.w * w0[3].w;
                acc[i][4] += a.x * w1[0].x + a.y * w1[1].x + a.z * w1[2].x + a.w * w1[3].x;
                acc[i][5] += a.x * w1[0].y + a.y * w1[1].y + a.z * w1[2].y + a.w * w1[3].y;
                acc[i][6] += a.x * w1[0].z + a.y * w1[1].z + a.z * w1[2].z + a.w * w1[3].z;
                acc[i][7] += a.x * w1[0].w + a.y * w1[1].w + a.z * w1[2].w + a.w * w1[3].w;
            }
        }

        const float* Bv = Bp[wi];
        float* Ov = Op[wi];
        #pragma unroll
        for (int i = 0; i < 4; i++) {
            float rri = rr[r0 + i];
            size_t grow = (size_t)(row0 + r0 + i) * 128;
            float vout[8];
            #pragma unroll
            for (int j = 0; j < 8; j++) {
                float v = acc[i][j] * rri + Bv[c0 + j];
                if (act == 1) {
                    v = v * __fdividef(1.0f, 1.0f + __expf(-v));
                } else if (act == 2) {
                    v = 0.5f * v * (1.0f + erff(v * 0.70710678118654752f));
                }
                vout[j] = v;
            }
            if (res) {
                #pragma unroll
                for (int j = 0; j < 8; j++) vout[j] += res[grow + c0 + j];
            }
            *(float4*)(Ov + grow + c0)     = make_float4(vout[0], vout[1], vout[2], vout[3]);
            *(float4*)(Ov + grow + c0 + 4) = make_float4(vout[4], vout[5], vout[6], vout[7]);
        }
        __syncthreads();
    }
}

// ===========================================================================
// HMMA HSTU attention (mma.sync bf16, hi/lo 3-pass split — fp32-accurate)
// grid = (8, 16), block = 256 (8 warps x m16 rows = 128-row tile).
// Block handles q-tiles qp and 15-qp (causal load balancing).
// ===========================================================================
#define QKP 72                 // row pitch in bf16 elements (144B -> conflict-free)
#define SM_QH 0
#define SM_QL 18432
#define SM_KH 36864
#define SM_KL 55296
#define SM_VH 73728
#define SM_VL 92160
#define ATTN_SMEM 110592

__global__ void __launch_bounds__(256, 1)
attn_hmma(const float* __restrict__ Q, const float* __restrict__ K,
          const float* __restrict__ V, float* __restrict__ O) {
    extern __shared__ char smc[];
    uint32_t sb = smem_u32(smc);

    int tid  = threadIdx.x;
    int warp = tid >> 5;       // 0..7
    int lane = tid & 31;
    int g    = lane >> 2;      // fragment group row 0..7
    int c2   = lane & 3;       // fragment group col 0..3
    int m0   = warp * 16;      // warp's S/O row base (0..112)

    int bh = blockIdx.y;
    int b = bh >> 1, h = bh & 1;
    int coloff = h * HD_;
    int qp = blockIdx.x;

    const float scale = 0.125f;   // folded into Q

    for (int half = 0; half < 2; half++) {
        int qt = half ? (15 - qp) : qp;
        int qbase = b * T_ + qt * 128;

        __syncthreads();   // previous Q-tile consumers done

        // ---- load Q tile -> smem as bf16 hi/lo, scale folded ----
        for (int idx = tid; idx < 128 * 16; idx += 256) {
            int r = idx >> 4, c4 = (idx & 15) << 2;
            float4 qv = *(const float4*)(Q + (size_t)(qbase + r) * 128 + coloff + c4);
            unsigned short h0, l0, h1, l1, h2, l2, h3, l3;
            split_bf16(qv.x * scale, h0, l0);
            split_bf16(qv.y * scale, h1, l1);
            split_bf16(qv.z * scale, h2, l2);
            split_bf16(qv.w * scale, h3, l3);
            uint32_t off = (uint32_t)(r * QKP + c4) * 2;
            *(uint2*)(smc + SM_QH + off) =
                make_uint2((uint32_t)h0 | ((uint32_t)h1 << 16),
                           (uint32_t)h2 | ((uint32_t)h3 << 16));
            *(uint2*)(smc + SM_QL + off) =
                make_uint2((uint32_t)l0 | ((uint32_t)l1 << 16),
                           (uint32_t)l2 | ((uint32_t)l3 << 16));
        }
        __syncthreads();

        // ---- A fragments for this warp's 16 Q rows (resident) ----
        uint32_t Ah[4][4], Al[4][4];
        #pragma unroll
        for (int ks = 0; ks < 4; ks++) {
            uint32_t o00 = (uint32_t)((m0 + g)     * QKP + 16 * ks + 2 * c2) * 2;
            uint32_t o01 = (uint32_t)((m0 + g + 8) * QKP + 16 * ks + 2 * c2) * 2;
            Ah[ks][0] = *(const uint32_t*)(smc + SM_QH + o00);
            Ah[ks][1] = *(const uint32_t*)(smc + SM_QH + o01);
            Ah[ks][2] = *(const uint32_t*)(smc + SM_QH + o00 + 16);
            Ah[ks][3] = *(const uint32_t*)(smc + SM_QH + o01 + 16);
            Al[ks][0] = *(const uint32_t*)(smc + SM_QL + o00);
            Al[ks][1] = *(const uint32_t*)(smc + SM_QL + o01);
            Al[ks][2] = *(const uint32_t*)(smc + SM_QL + o00 + 16);
            Al[ks][3] = *(const uint32_t*)(smc + SM_QL + o01 + 16);
        }

        float Of[8][4];
        #pragma unroll
        for (int nf = 0; nf < 8; nf++)
            #pragma unroll
            for (int r = 0; r < 4; r++) Of[nf][r] = 0.0f;
        float ds0 = 0.0f, ds1 = 0.0f;

        int row0 = qt * 128 + m0 + g;       // global (in-seq) rows of this lane
        int row1 = row0 + 8;

        for (int kt = 0; kt <= qt; kt++) {
            int kbase = b * T_ + kt * 128;
            __syncthreads();   // previous K/V consumers done

            // ---- K and V tiles -> smem bf16 hi/lo ----
            for (int idx = tid; idx < 128 * 16; idx += 256) {
                int r = idx >> 4, c4 = (idx & 15) << 2;
                uint32_t off = (uint32_t)(r * QKP + c4) * 2;
                {
                    float4 kv = *(const float4*)(K + (size_t)(kbase + r) * 128 + coloff + c4);
                    unsigned short h0, l0, h1, l1, h2, l2, h3, l3;
                    split_bf16(kv.x, h0, l0);
                    split_bf16(kv.y, h1, l1);
                    split_bf16(kv.z, h2, l2);
                    split_bf16(kv.w, h3, l3);
                    *(uint2*)(smc + SM_KH + off) =
                        make_uint2((uint32_t)h0 | ((uint32_t)h1 << 16),
                                   (uint32_t)h2 | ((uint32_t)h3 << 16));
                    *(uint2*)(smc + SM_KL + off) =
                        make_uint2((uint32_t)l0 | ((uint32_t)l1 << 16),
                                   (uint32_t)l2 | ((uint32_t)l3 << 16));
                }
                {
                    float4 vv = *(const float4*)(V + (size_t)(kbase + r) * 128 + coloff + c4);
                    unsigned short h0, l0, h1, l1, h2, l2, h3, l3;
                    split_bf16(vv.x, h0, l0);
                    split_bf16(vv.y, h1, l1);
                    split_bf16(vv.z, h2, l2);
                    split_bf16(vv.w, h3, l3);
                    *(uint2*)(smc + SM_VH + off) =
                        make_uint2((uint32_t)h0 | ((uint32_t)h1 << 16),
                                   (uint32_t)h2 | ((uint32_t)h3 << 16));
                    *(uint2*)(smc + SM_VL + off) =
                        make_uint2((uint32_t)l0 | ((uint32_t)l1 << 16),
                                   (uint32_t)l2 | ((uint32_t)l3 << 16));
                }
            }
            __syncthreads();

            // ---- process in two S-column halves to bound registers ----
            #pragma unroll
            for (int sh = 0; sh < 2; sh++) {
                uint32_t Phi[4][4], Plo[4][4];

                // S = Q @ K^T for cols [64*sh, 64*sh+64), gate, pack P frags
                #pragma unroll
                for (int jj = 0; jj < 4; jj++) {
                    int jpv = 4 * sh + jj;      // PV k-step index (0..7)
                    #pragma unroll
                    for (int e = 0; e < 2; e++) {
                        int nfr = 2 * jpv + e;  // S n-fragment (0..15)
                        float cf[4] = {0.0f, 0.0f, 0.0f, 0.0f};
                        uint32_t kb = (uint32_t)((8 * nfr + g) * QKP + 2 * c2) * 2;
                        #pragma unroll
                        for (int ks = 0; ks < 4; ks++) {
                            uint32_t o = kb + 32 * ks;
                            uint32_t bh0 = *(const uint32_t*)(smc + SM_KH + o);
                            uint32_t bh1 = *(const uint32_t*)(smc + SM_KH + o + 16);
                            uint32_t bl0 = *(const uint32_t*)(smc + SM_KL + o);
                            uint32_t bl1 = *(const uint32_t*)(smc + SM_KL + o + 16);
                            mma16816(cf, Ah[ks], bh0, bh1);
                            mma16816(cf, Ah[ks], bl0, bl1);
                            mma16816(cf, Al[ks], bh0, bh1);
                        }
                        // gate: max(silu(a),0) with causal mask (always valid)
                        int colb = kt * 128 + 8 * nfr + 2 * c2;
                        float g0 = 0.0f, g1 = 0.0f, g2 = 0.0f, g3 = 0.0f;
                        if (cf[0] > 0.0f && colb     <= row0)
                            g0 = cf[0] * __fdividef(1.0f, 1.0f + __expf(-cf[0]));
                        if (cf[1] > 0.0f && colb + 1 <= row0)
                            g1 = cf[1] * __fdividef(1.0f, 1.0f + __expf(-cf[1]));
                        if (cf[2] > 0.0f && colb     <= row1)
                            g2 = cf[2] * __fdividef(1.0f, 1.0f + __expf(-cf[2]));
                        if (cf[3] > 0.0f && colb + 1 <= row1)
                            g3 = cf[3] * __fdividef(1.0f, 1.0f + __expf(-cf[3]));
                        ds0 += g0 + g1;
                        ds1 += g2 + g3;
                        Phi[jj][2 * e]     = bf16x2_hi(g0, g1);
                        Phi[jj][2 * e + 1] = bf16x2_hi(g2, g3);
                        Plo[jj][2 * e]     = bf16x2_lo(g0, g1);
                        Plo[jj][2 * e + 1] = bf16x2_lo(g2, g3);
                    }
                }

                // O += P @ V for this k-half
                #pragma unroll
                for (int jj = 0; jj < 4; jj++) {
                    int k0v = 16 * (4 * sh + jj);
                    uint32_t rowa = (uint32_t)((k0v + (lane & 15)) * QKP) * 2;
                    #pragma unroll
                    for (int nf = 0; nf < 8; nf++) {
                        uint32_t addr_h = sb + SM_VH + rowa + (uint32_t)(16 * nf);
                        uint32_t addr_l = sb + SM_VL + rowa + (uint32_t)(16 * nf);
                        uint32_t vh0, vh1, vl0, vl1;
                        ldsm_x2_trans(vh0, vh1, addr_h);
                        ldsm_x2_trans(vl0, vl1, addr_l);
                        mma16816(Of[nf], Phi[jj], vh0, vh1);
                        mma16816(Of[nf], Phi[jj], vl0, vl1);
                        mma16816(Of[nf], Plo[jj], vh0, vh1);
                    }
                }
            }
        }

        // ---- row denominators (reduce across the 4-lane quad) ----
        ds0 += __shfl_xor_sync(0xffffffffu, ds0, 1);
        ds0 += __shfl_xor_sync(0xffffffffu, ds0, 2);
        ds1 += __shfl_xor_sync(0xffffffffu, ds1, 1);
        ds1 += __shfl_xor_sync(0xffffffffu, ds1, 2);
        float f0 = (ds0 > 1e-12f) ? __fdividef(1.0f, ds0 + EPS_) : 0.0f;
        float f1 = (ds1 > 1e-12f) ? __fdividef(1.0f, ds1 + EPS_) : 0.0f;

        // ---- write O ----
        size_t orow0 = (size_t)(qbase + m0 + g) * 128 + coloff;
        size_t orow1 = orow0 + 8 * 128;
        #pragma unroll
        for (int nf = 0; nf < 8; nf++) {
            int c = 8 * nf + 2 * c2;
            *(float2*)(O + orow0 + c) = make_float2(Of[nf][0] * f0, Of[nf][1] * f0);
            *(float2*)(O + orow1 + c) = make_float2(Of[nf][2] * f1, Of[nf][3] * f1);
        }
    }
}

// ===========================================================================
// Host orchestration
// ===========================================================================
extern "C" void kernel_launch(void* const* d_in, const int* in_sizes, int n_in,
                              void* d_out, int out_size) {
    const int*   seq    = (const int*)  d_in[0];
    // d_in[1] = attn_mask (causal tril) — synthesized in-kernel
    const float* item   = (const float*)d_in[2];
    const float* pos    = (const float*)d_in[3];
    const float* emb_s  = (const float*)d_in[4];
    const float* ln1    = (const float*)d_in[5];
    const float* Uw     = (const float*)d_in[6];
    const float* Ub     = (const float*)d_in[7];
    const float* Vw     = (const float*)d_in[8];
    const float* Vb     = (const float*)d_in[9];
    const float* Qw     = (const float*)d_in[10];
    const float* Qb     = (const float*)d_in[11];
    const float* Kw     = (const float*)d_in[12];
    const float* Kb     = (const float*)d_in[13];
    const float* f2w    = (const float*)d_in[14];
    const float* f2b    = (const float*)d_in[15];
    const float* hstu   = (const float*)d_in[16];
    const float* ln2    = (const float*)d_in[17];
    const float* c1w    = (const float*)d_in[18];
    const float* c1b    = (const float*)d_in[19];
    const float* c2w    = (const float*)d_in[20];
    const float* c2b    = (const float*)d_in[21];
    const float* last_s = (const float*)d_in[22];
    float* out = (float*)d_out;

    float *x, *u, *v, *q, *k, *av, *tb;
    cudaGetSymbolAddress((void**)&x,  g_x);
    cudaGetSymbolAddress((void**)&u,  g_u);
    cudaGetSymbolAddress((void**)&v,  g_v);
    cudaGetSymbolAddress((void**)&q,  g_q);
    cudaGetSymbolAddress((void**)&k,  g_k);
    cudaGetSymbolAddress((void**)&av, g_av);
    cudaGetSymbolAddress((void**)&tb, g_t);

    cudaFuncSetAttribute(fused_gemm,
                         cudaFuncAttributeMaxDynamicSharedMemorySize, GEMM_SMEM);
    cudaFuncSetAttribute(attn_hmma,
                         cudaFuncAttributeMaxDynamicSharedMemorySize, ATTN_SMEM);

    dim3 gemmGrid(BT_ / 128);
    dim3 attnGrid(8, B_ * H_);

    embed_rms_kernel<<<BT_ / 8, 256>>>(seq, item, pos, emb_s, x);

    for (int l = 0; l < L_; l++) {
        size_t wo = (size_t)l * D_ * D_;
        size_t bo = (size_t)l * D_;

        fused_gemm<<<gemmGrid, 512, GEMM_SMEM>>>(
            x, nullptr, ln1 + bo, 1,
            Uw + wo, Ub + bo, u,
            Vw + wo, Vb + bo, v,
            Qw + wo, Qb + bo, q,
            Kw + wo, Kb + bo, k,
            nullptr, 4, 1);

        attn_hmma<<<attnGrid, 256, ATTN_SMEM>>>(q, k, v, av);

        fused_gemm<<<gemmGrid, 512, GEMM_SMEM>>>(
            av, u, hstu + bo, 1,
            f2w + wo, f2b + bo, x,
            nullptr, nullptr, nullptr,
            nullptr, nullptr, nullptr,
            nullptr, nullptr, nullptr,
            x, 1, 0);

        fused_gemm<<<gemmGrid, 512, GEMM_SMEM>>>(
            x, nullptr, ln2 + bo, 1,
            c1w + wo, c1b + bo, tb,
            nullptr, nullptr, nullptr,
            nullptr, nullptr, nullptr,
            nullptr, nullptr, nullptr,
            nullptr, 1, 2);

        fused_gemm<<<gemmGrid, 512, GEMM_SMEM>>>(
            tb, nullptr, nullptr, 0,
            c2w + wo, c2b + bo, x,
            nullptr, nullptr, nullptr,
            nullptr, nullptr, nullptr,
            nullptr, nullptr, nullptr,
            x, 1, 0);
    }

    rms_kernel<<<BT_ / 8, 256>>>(x, last_s, out);
}

// round 7
// speedup vs baseline: 2.0600x; 1.1219x over previous
#include <cuda_runtime.h>
#include <cuda_bf16.h>
#include <math.h>
#include <stdint.h>

// Problem constants
#define B_ 8
#define T_ 2048
#define D_ 128
#define L_ 4
#define H_ 2
#define HD_ 64
#define BT_ (B_ * T_)          // 16384 rows
#define EPS_ 1e-8f

#define GP 132                 // smem pitch (floats) for 128-wide gemm tiles
#define GEMM_SMEM ((2 * 128 * GP + 128) * 4)

// ---------------------------------------------------------------------------
// Scratch buffers (allocation-free: __device__ globals)
// ---------------------------------------------------------------------------
__device__ float g_x [BT_ * D_];
__device__ float g_u [BT_ * D_];
__device__ float g_v [BT_ * D_];
__device__ float g_q [BT_ * D_];
__device__ float g_k [BT_ * D_];
__device__ float g_av[BT_ * D_];
__device__ float g_t [BT_ * D_];

// ===========================================================================
// Small helpers
// ===========================================================================
__device__ __forceinline__ uint32_t smem_u32(const void* p) {
    uint32_t a;
    asm("{ .reg .u64 t; cvta.to.shared.u64 t, %1; cvt.u32.u64 %0, t; }"
        : "=r"(a) : "l"(p));
    return a;
}

// bf16 hi/lo split of an fp32 value
__device__ __forceinline__ void split_bf16(float x, unsigned short& h, unsigned short& l) {
    __nv_bfloat16 hb = __float2bfloat16(x);
    float hf = __bfloat162float(hb);
    __nv_bfloat16 lb = __float2bfloat16(x - hf);
    h = __bfloat16_as_ushort(hb);
    l = __bfloat16_as_ushort(lb);
}

__device__ __forceinline__ uint32_t bf16x2_hi(float x, float y) {
    __nv_bfloat162 t = __floats2bfloat162_rn(x, y);  // .x = x in low half
    return *reinterpret_cast<uint32_t*>(&t);
}
__device__ __forceinline__ uint32_t bf16x2_lo(float x, float y) {
    float xh = __bfloat162float(__float2bfloat16(x));
    float yh = __bfloat162float(__float2bfloat16(y));
    __nv_bfloat162 t = __floats2bfloat162_rn(x - xh, y - yh);
    return *reinterpret_cast<uint32_t*>(&t);
}

// mma.sync m16n8k16 bf16 -> f32 (accumulate in place)
__device__ __forceinline__ void mma16816(float* c, const uint32_t* a,
                                         uint32_t b0, uint32_t b1) {
    asm volatile(
        "mma.sync.aligned.m16n8k16.row.col.f32.bf16.bf16.f32 "
        "{%0,%1,%2,%3}, {%4,%5,%6,%7}, {%8,%9}, {%0,%1,%2,%3};"
        : "+f"(c[0]), "+f"(c[1]), "+f"(c[2]), "+f"(c[3])
        : "r"(a[0]), "r"(a[1]), "r"(a[2]), "r"(a[3]), "r"(b0), "r"(b1));
}

// ldmatrix x2 transposed (for V B-fragments from row-major V[key][d])
__device__ __forceinline__ void ldsm_x2_trans(uint32_t& r0, uint32_t& r1, uint32_t addr) {
    asm volatile("ldmatrix.sync.aligned.m8n8.x2.trans.shared.b16 {%0,%1}, [%2];"
                 : "=r"(r0), "=r"(r1) : "r"(addr));
}

// ===========================================================================
// Elementwise RMS kernels
// ===========================================================================
__global__ void rms_kernel(const float* __restrict__ in,
                           const float* __restrict__ sc,
                           float* __restrict__ out) {
    int warp = threadIdx.x >> 5, lane = threadIdx.x & 31;
    size_t row = (size_t)blockIdx.x * 8 + warp;
    float4 v = *(const float4*)(in + row * 128 + lane * 4);
    float ss = v.x * v.x + v.y * v.y + v.z * v.z + v.w * v.w;
    #pragma unroll
    for (int o = 16; o > 0; o >>= 1) ss += __shfl_xor_sync(0xffffffffu, ss, o);
    float r = rsqrtf(ss * (1.0f / 128.0f) + EPS_);
    float4 s = *(const float4*)(sc + lane * 4);
    *(float4*)(out + row * 128 + lane * 4) =
        make_float4(v.x * r * s.x, v.y * r * s.y, v.z * r * s.z, v.w * r * s.w);
}

__global__ void embed_rms_kernel(const int* __restrict__ seq,
                                 const float* __restrict__ item,
                                 const float* __restrict__ pos,
                                 const float* __restrict__ sc,
                                 float* __restrict__ out) {
    int warp = threadIdx.x >> 5, lane = threadIdx.x & 31;
    size_t row = (size_t)blockIdx.x * 8 + warp;
    int t = (int)(row & (T_ - 1));
    int id = seq[row];
    float4 a = *(const float4*)(item + (size_t)id * 128 + lane * 4);
    float4 p = *(const float4*)(pos + (size_t)(t + 1) * 128 + lane * 4);
    float4 v = make_float4(a.x + p.x, a.y + p.y, a.z + p.z, a.w + p.w);
    float ss = v.x * v.x + v.y * v.y + v.z * v.z + v.w * v.w;
    #pragma unroll
    for (int o = 16; o > 0; o >>= 1) ss += __shfl_xor_sync(0xffffffffu, ss, o);
    float r = rsqrtf(ss * (1.0f / 128.0f) + EPS_);
    float4 s = *(const float4*)(sc + lane * 4);
    *(float4*)(out + row * 128 + lane * 4) =
        make_float4(v.x * r * s.x, v.y * r * s.y, v.z * r * s.z, v.w * r * s.w);
}

// ===========================================================================
// Fused GEMM (fp32 SIMT, known good)
// ===========================================================================
__global__ void __launch_bounds__(512)
fused_gemm(const float* __restrict__ A,
           const float* __restrict__ mul,
           const float* __restrict__ scvec,
           int use_rms,
           const float* __restrict__ W0, const float* __restrict__ B0, float* __restrict__ O0,
           const float* __restrict__ W1, const float* __restrict__ B1, float* __restrict__ O1,
           const float* __restrict__ W2, const float* __restrict__ B2, float* __restrict__ O2,
           const float* __restrict__ W3, const float* __restrict__ B3, float* __restrict__ O3,
           const float* __restrict__ res,
           int nw, int act) {
    extern __shared__ float sm[];
    float* As = sm;
    float* Ws = As + 128 * GP;
    float* rr = Ws + 128 * GP;

    int tid = threadIdx.x;
    int row0 = blockIdx.x * 128;

    for (int idx = tid; idx < 128 * 32; idx += 512) {
        int r = idx >> 5, c4 = (idx & 31) << 2;
        *(float4*)(As + r * GP + c4) =
            *(const float4*)(A + (size_t)(row0 + r) * 128 + c4);
    }
    __syncthreads();

    if (use_rms) {
        int w = tid >> 5, lane = tid & 31;
        for (int r = w; r < 128; r += 16) {
            float4 v = *(const float4*)(As + r * GP + lane * 4);
            float ss = v.x * v.x + v.y * v.y + v.z * v.z + v.w * v.w;
            #pragma unroll
            for (int off = 16; off > 0; off >>= 1)
                ss += __shfl_xor_sync(0xffffffffu, ss, off);
            if (lane == 0) rr[r] = rsqrtf(ss * (1.0f / 128.0f) + EPS_);
        }
    } else {
        if (tid < 128) rr[tid] = 1.0f;
    }
    __syncthreads();

    if (mul) {
        for (int idx = tid; idx < 128 * 32; idx += 512) {
            int r = idx >> 5, c4 = (idx & 31) << 2;
            float4 m = *(const float4*)(mul + (size_t)(row0 + r) * 128 + c4);
            float4 a = *(float4*)(As + r * GP + c4);
            a.x *= m.x; a.y *= m.y; a.z *= m.z; a.w *= m.w;
            *(float4*)(As + r * GP + c4) = a;
        }
    }

    int ti = tid >> 4, tj = tid & 15;
    int r0 = ti * 4, c0 = tj * 8;

    const float* Wp[4] = {W0, W1, W2, W3};
    const float* Bp[4] = {B0, B1, B2, B3};
    float*       Op[4] = {O0, O1, O2, O3};

    for (int wi = 0; wi < nw; wi++) {
        const float* W = Wp[wi];
        for (int idx = tid; idx < 128 * 32; idx += 512) {
            int r = idx >> 5, c4 = (idx & 31) << 2;
            float s = scvec ? scvec[r] : 1.0f;
            float4 v = *(const float4*)(W + (size_t)r * 128 + c4);
            v.x *= s; v.y *= s; v.z *= s; v.w *= s;
            *(float4*)(Ws + r * GP + c4) = v;
        }
        __syncthreads();

        float acc[4][8];
        #pragma unroll
        for (int i = 0; i < 4; i++)
            #pragma unroll
            for (int j = 0; j < 8; j++) acc[i][j] = 0.0f;

        for (int k = 0; k < 128; k += 4) {
            float4 w0[4], w1[4];
            #pragma unroll
            for (int kk = 0; kk < 4; kk++) {
                w0[kk] = *(const float4*)(Ws + (k + kk) * GP + c0);
                w1[kk] = *(const float4*)(Ws + (k + kk) * GP + c0 + 4);
            }
            #pragma unroll
            for (int i = 0; i < 4; i++) {
                float4 a = *(const float4*)(As + (r0 + i) * GP + k);
                acc[i][0] += a.x * w0[0].x + a.y * w0[1].x + a.z * w0[2].x + a.w * w0[3].x;
                acc[i][1] += a.x * w0[0].y + a.y * w0[1].y + a.z * w0[2].y + a.w * w0[3].y;
                acc[i][2] += a.x * w0[0].z + a.y * w0[1].z + a.z * w0[2].z + a.w * w0[3].z;
                acc[i][3] += a.x * w0[0].w + a.y * w0[1].w + a.z * w0[2].w + a.w * w0[3].w;
                acc[i][4] += a.x * w1[0].x + a.y * w1[1].x + a.z * w1[2].x + a.w * w1[3].x;
                acc[i][5] += a.x * w1[0].y + a.y * w1[1].y + a.z * w1[2].y + a.w * w1[3].y;
                acc[i][6] += a.x * w1[0].z + a.y * w1[1].z + a.z * w1[2].z + a.w * w1[3].z;
                acc[i][7] += a.x * w1[0].w + a.y * w1[1].w + a.z * w1[2].w + a.w * w1[3].w;
            }
        }

        const float* Bv = Bp[wi];
        float* Ov = Op[wi];
        #pragma unroll
        for (int i = 0; i < 4; i++) {
            float rri = rr[r0 + i];
            size_t grow = (size_t)(row0 + r0 + i) * 128;
            float vout[8];
            #pragma unroll
            for (int j = 0; j < 8; j++) {
                float v = acc[i][j] * rri + Bv[c0 + j];
                if (act == 1) {
                    v = v * __fdividef(1.0f, 1.0f + __expf(-v));
                } else if (act == 2) {
                    v = 0.5f * v * (1.0f + erff(v * 0.70710678118654752f));
                }
                vout[j] = v;
            }
            if (res) {
                #pragma unroll
                for (int j = 0; j < 8; j++) vout[j] += res[grow + c0 + j];
            }
            *(float4*)(Ov + grow + c0)     = make_float4(vout[0], vout[1], vout[2], vout[3]);
            *(float4*)(Ov + grow + c0 + 4) = make_float4(vout[4], vout[5], vout[6], vout[7]);
        }
        __syncthreads();
    }
}

// ===========================================================================
// HMMA HSTU attention (mma.sync bf16, hi/lo 3-pass split — fp32-accurate)
// grid = (8, 16), block = 512 (16 warps).
// Warp pair (2p, 2p+1) owns Q-rows [16p,16p+16); the two warps split the
// 128 S-columns / PV k-range in half (sh = warp&1). O partials and row
// denominators are combined through smem once per q-tile.
// Block handles q-tiles qp and 15-qp (causal load balancing).
// ===========================================================================
#define QKP 72                 // row pitch in bf16 elements (144B -> conflict-free)
#define SM_QH 0
#define SM_QL 18432
#define SM_KH 36864            // reused as O-combine scratch between k-loops
#define SM_KL 55296
#define SM_VH 73728
#define SM_VL 92160
#define ATTN_SMEM 110592
// scratch layout (inside SM_KH region): per pair p at SM_KH + p*4352:
//   [0,4096)    : 32 lanes x 32 floats (Of partial of odd warp)
//   [4096,4352) : 32 lanes x 2 floats (ds0, ds1 of odd warp)

__global__ void __launch_bounds__(512, 1)
attn_hmma(const float* __restrict__ Q, const float* __restrict__ K,
          const float* __restrict__ V, float* __restrict__ O) {
    extern __shared__ char smc[];
    uint32_t sb = smem_u32(smc);

    int tid  = threadIdx.x;
    int warp = tid >> 5;       // 0..15
    int lane = tid & 31;
    int pair = warp >> 1;      // 0..7
    int sh   = warp & 1;       // column half
    int g    = lane >> 2;      // fragment group row 0..7
    int c2   = lane & 3;       // fragment group col 0..3
    int m0   = pair * 16;      // pair's S/O row base (0..112)

    int bh = blockIdx.y;
    int b = bh >> 1, h = bh & 1;
    int coloff = h * HD_;
    int qp = blockIdx.x;

    const float scale = 0.125f;   // folded into Q

    for (int half = 0; half < 2; half++) {
        int qt = half ? (15 - qp) : qp;
        int qbase = b * T_ + qt * 128;

        __syncthreads();   // previous Q-tile consumers / scratch users done

        // ---- load Q tile -> smem as bf16 hi/lo, scale folded ----
        for (int idx = tid; idx < 128 * 16; idx += 512) {
            int r = idx >> 4, c4 = (idx & 15) << 2;
            float4 qv = *(const float4*)(Q + (size_t)(qbase + r) * 128 + coloff + c4);
            unsigned short h0, l0, h1, l1, h2, l2, h3, l3;
            split_bf16(qv.x * scale, h0, l0);
            split_bf16(qv.y * scale, h1, l1);
            split_bf16(qv.z * scale, h2, l2);
            split_bf16(qv.w * scale, h3, l3);
            uint32_t off = (uint32_t)(r * QKP + c4) * 2;
            *(uint2*)(smc + SM_QH + off) =
                make_uint2((uint32_t)h0 | ((uint32_t)h1 << 16),
                           (uint32_t)h2 | ((uint32_t)h3 << 16));
            *(uint2*)(smc + SM_QL + off) =
                make_uint2((uint32_t)l0 | ((uint32_t)l1 << 16),
                           (uint32_t)l2 | ((uint32_t)l3 << 16));
        }
        __syncthreads();

        // ---- A fragments for this pair's 16 Q rows (resident per warp) ----
        uint32_t Ah[4][4], Al[4][4];
        #pragma unroll
        for (int ks = 0; ks < 4; ks++) {
            uint32_t o00 = (uint32_t)((m0 + g)     * QKP + 16 * ks + 2 * c2) * 2;
            uint32_t o01 = (uint32_t)((m0 + g + 8) * QKP + 16 * ks + 2 * c2) * 2;
            Ah[ks][0] = *(const uint32_t*)(smc + SM_QH + o00);
            Ah[ks][1] = *(const uint32_t*)(smc + SM_QH + o01);
            Ah[ks][2] = *(const uint32_t*)(smc + SM_QH + o00 + 16);
            Ah[ks][3] = *(const uint32_t*)(smc + SM_QH + o01 + 16);
            Al[ks][0] = *(const uint32_t*)(smc + SM_QL + o00);
            Al[ks][1] = *(const uint32_t*)(smc + SM_QL + o01);
            Al[ks][2] = *(const uint32_t*)(smc + SM_QL + o00 + 16);
            Al[ks][3] = *(const uint32_t*)(smc + SM_QL + o01 + 16);
        }

        float Of[8][4];
        #pragma unroll
        for (int nf = 0; nf < 8; nf++)
            #pragma unroll
            for (int r = 0; r < 4; r++) Of[nf][r] = 0.0f;
        float ds0 = 0.0f, ds1 = 0.0f;

        int row0 = qt * 128 + m0 + g;       // global (in-seq) rows of this lane
        int row1 = row0 + 8;

        for (int kt = 0; kt <= qt; kt++) {
            int kbase = b * T_ + kt * 128;
            __syncthreads();   // previous K/V consumers done

            // ---- K and V tiles -> smem bf16 hi/lo ----
            for (int idx = tid; idx < 128 * 16; idx += 512) {
                int r = idx >> 4, c4 = (idx & 15) << 2;
                uint32_t off = (uint32_t)(r * QKP + c4) * 2;
                {
                    float4 kv = *(const float4*)(K + (size_t)(kbase + r) * 128 + coloff + c4);
                    unsigned short h0, l0, h1, l1, h2, l2, h3, l3;
                    split_bf16(kv.x, h0, l0);
                    split_bf16(kv.y, h1, l1);
                    split_bf16(kv.z, h2, l2);
                    split_bf16(kv.w, h3, l3);
                    *(uint2*)(smc + SM_KH + off) =
                        make_uint2((uint32_t)h0 | ((uint32_t)h1 << 16),
                                   (uint32_t)h2 | ((uint32_t)h3 << 16));
                    *(uint2*)(smc + SM_KL + off) =
                        make_uint2((uint32_t)l0 | ((uint32_t)l1 << 16),
                                   (uint32_t)l2 | ((uint32_t)l3 << 16));
                }
                {
                    float4 vv = *(const float4*)(V + (size_t)(kbase + r) * 128 + coloff + c4);
                    unsigned short h0, l0, h1, l1, h2, l2, h3, l3;
                    split_bf16(vv.x, h0, l0);
                    split_bf16(vv.y, h1, l1);
                    split_bf16(vv.z, h2, l2);
                    split_bf16(vv.w, h3, l3);
                    *(uint2*)(smc + SM_VH + off) =
                        make_uint2((uint32_t)h0 | ((uint32_t)h1 << 16),
                                   (uint32_t)h2 | ((uint32_t)h3 << 16));
                    *(uint2*)(smc + SM_VL + off) =
                        make_uint2((uint32_t)l0 | ((uint32_t)l1 << 16),
                                   (uint32_t)l2 | ((uint32_t)l3 << 16));
                }
            }
            __syncthreads();

            // ---- this warp's S-column half ----
            uint32_t Phi[4][4], Plo[4][4];

            // S = Q @ K^T for cols [64*sh, 64*sh+64), gate, pack P frags
            #pragma unroll
            for (int jj = 0; jj < 4; jj++) {
                int jpv = 4 * sh + jj;      // PV k-step index (0..7)
                #pragma unroll
                for (int e = 0; e < 2; e++) {
                    int nfr = 2 * jpv + e;  // S n-fragment (0..15)
                    float cf[4] = {0.0f, 0.0f, 0.0f, 0.0f};
                    uint32_t kb = (uint32_t)((8 * nfr + g) * QKP + 2 * c2) * 2;
                    #pragma unroll
                    for (int ks = 0; ks < 4; ks++) {
                        uint32_t o = kb + 32 * ks;
                        uint32_t bh0 = *(const uint32_t*)(smc + SM_KH + o);
                        uint32_t bh1 = *(const uint32_t*)(smc + SM_KH + o + 16);
                        uint32_t bl0 = *(const uint32_t*)(smc + SM_KL + o);
                        uint32_t bl1 = *(const uint32_t*)(smc + SM_KL + o + 16);
                        mma16816(cf, Ah[ks], bh0, bh1);
                        mma16816(cf, Ah[ks], bl0, bl1);
                        mma16816(cf, Al[ks], bh0, bh1);
                    }
                    // gate: max(silu(a),0) with causal mask (always valid)
                    int colb = kt * 128 + 8 * nfr + 2 * c2;
                    float g0 = 0.0f, g1 = 0.0f, g2 = 0.0f, g3 = 0.0f;
                    if (cf[0] > 0.0f && colb     <= row0)
                        g0 = cf[0] * __fdividef(1.0f, 1.0f + __expf(-cf[0]));
                    if (cf[1] > 0.0f && colb + 1 <= row0)
                        g1 = cf[1] * __fdividef(1.0f, 1.0f + __expf(-cf[1]));
                    if (cf[2] > 0.0f && colb     <= row1)
                        g2 = cf[2] * __fdividef(1.0f, 1.0f + __expf(-cf[2]));
                    if (cf[3] > 0.0f && colb + 1 <= row1)
                        g3 = cf[3] * __fdividef(1.0f, 1.0f + __expf(-cf[3]));
                    ds0 += g0 + g1;
                    ds1 += g2 + g3;
                    Phi[jj][2 * e]     = bf16x2_hi(g0, g1);
                    Phi[jj][2 * e + 1] = bf16x2_hi(g2, g3);
                    Plo[jj][2 * e]     = bf16x2_lo(g0, g1);
                    Plo[jj][2 * e + 1] = bf16x2_lo(g2, g3);
                }
            }

            // O += P @ V for this warp's k-half
            #pragma unroll
            for (int jj = 0; jj < 4; jj++) {
                int k0v = 16 * (4 * sh + jj);
                uint32_t rowa = (uint32_t)((k0v + (lane & 15)) * QKP) * 2;
                #pragma unroll
                for (int nf = 0; nf < 8; nf++) {
                    uint32_t addr_h = sb + SM_VH + rowa + (uint32_t)(16 * nf);
                    uint32_t addr_l = sb + SM_VL + rowa + (uint32_t)(16 * nf);
                    uint32_t vh0, vh1, vl0, vl1;
                    ldsm_x2_trans(vh0, vh1, addr_h);
                    ldsm_x2_trans(vl0, vl1, addr_l);
                    mma16816(Of[nf], Phi[jj], vh0, vh1);
                    mma16816(Of[nf], Phi[jj], vl0, vl1);
                    mma16816(Of[nf], Plo[jj], vh0, vh1);
                }
            }
        }

        // ---- quad-reduce denominators within each warp ----
        ds0 += __shfl_xor_sync(0xffffffffu, ds0, 1);
        ds0 += __shfl_xor_sync(0xffffffffu, ds0, 2);
        ds1 += __shfl_xor_sync(0xffffffffu, ds1, 1);
        ds1 += __shfl_xor_sync(0xffffffffu, ds1, 2);

        // ---- combine the two column-half partials through smem scratch ----
        __syncthreads();   // all K-smem reads done; safe to reuse as scratch
        float* scr = (float*)(smc + SM_KH + pair * 4352);
        if (sh == 1) {
            float* dst = scr + lane * 32;
            #pragma unroll
            for (int nf = 0; nf < 8; nf++) {
                dst[4 * nf + 0] = Of[nf][0];
                dst[4 * nf + 1] = Of[nf][1];
                dst[4 * nf + 2] = Of[nf][2];
                dst[4 * nf + 3] = Of[nf][3];
            }
            scr[1024 + lane * 2]     = ds0;
            scr[1024 + lane * 2 + 1] = ds1;
        }
        __syncthreads();

        if (sh == 0) {
            const float* src = scr + lane * 32;
            float dt0 = ds0 + scr[1024 + lane * 2];
            float dt1 = ds1 + scr[1024 + lane * 2 + 1];
            float f0 = (dt0 > 1e-12f) ? __fdividef(1.0f, dt0 + EPS_) : 0.0f;
            float f1 = (dt1 > 1e-12f) ? __fdividef(1.0f, dt1 + EPS_) : 0.0f;

            size_t orow0 = (size_t)(qbase + m0 + g) * 128 + coloff;
            size_t orow1 = orow0 + 8 * 128;
            #pragma unroll
            for (int nf = 0; nf < 8; nf++) {
                int c = 8 * nf + 2 * c2;
                float o0 = Of[nf][0] + src[4 * nf + 0];
                float o1 = Of[nf][1] + src[4 * nf + 1];
                float o2 = Of[nf][2] + src[4 * nf + 2];
                float o3 = Of[nf][3] + src[4 * nf + 3];
                *(float2*)(O + orow0 + c) = make_float2(o0 * f0, o1 * f0);
                *(float2*)(O + orow1 + c) = make_float2(o2 * f1, o3 * f1);
            }
        }
    }
}

// ===========================================================================
// Host orchestration
// ===========================================================================
extern "C" void kernel_launch(void* const* d_in, const int* in_sizes, int n_in,
                              void* d_out, int out_size) {
    const int*   seq    = (const int*)  d_in[0];
    // d_in[1] = attn_mask (causal tril) — synthesized in-kernel
    const float* item   = (const float*)d_in[2];
    const float* pos    = (const float*)d_in[3];
    const float* emb_s  = (const float*)d_in[4];
    const float* ln1    = (const float*)d_in[5];
    const float* Uw     = (const float*)d_in[6];
    const float* Ub     = (const float*)d_in[7];
    const float* Vw     = (const float*)d_in[8];
    const float* Vb     = (const float*)d_in[9];
    const float* Qw     = (const float*)d_in[10];
    const float* Qb     = (const float*)d_in[11];
    const float* Kw     = (const float*)d_in[12];
    const float* Kb     = (const float*)d_in[13];
    const float* f2w    = (const float*)d_in[14];
    const float* f2b    = (const float*)d_in[15];
    const float* hstu   = (const float*)d_in[16];
    const float* ln2    = (const float*)d_in[17];
    const float* c1w    = (const float*)d_in[18];
    const float* c1b    = (const float*)d_in[19];
    const float* c2w    = (const float*)d_in[20];
    const float* c2b    = (const float*)d_in[21];
    const float* last_s = (const float*)d_in[22];
    float* out = (float*)d_out;

    float *x, *u, *v, *q, *k, *av, *tb;
    cudaGetSymbolAddress((void**)&x,  g_x);
    cudaGetSymbolAddress((void**)&u,  g_u);
    cudaGetSymbolAddress((void**)&v,  g_v);
    cudaGetSymbolAddress((void**)&q,  g_q);
    cudaGetSymbolAddress((void**)&k,  g_k);
    cudaGetSymbolAddress((void**)&av, g_av);
    cudaGetSymbolAddress((void**)&tb, g_t);

    cudaFuncSetAttribute(fused_gemm,
                         cudaFuncAttributeMaxDynamicSharedMemorySize, GEMM_SMEM);
    cudaFuncSetAttribute(attn_hmma,
                         cudaFuncAttributeMaxDynamicSharedMemorySize, ATTN_SMEM);

    dim3 gemmGrid(BT_ / 128);
    dim3 attnGrid(8, B_ * H_);

    embed_rms_kernel<<<BT_ / 8, 256>>>(seq, item, pos, emb_s, x);

    for (int l = 0; l < L_; l++) {
        size_t wo = (size_t)l * D_ * D_;
        size_t bo = (size_t)l * D_;

        fused_gemm<<<gemmGrid, 512, GEMM_SMEM>>>(
            x, nullptr, ln1 + bo, 1,
            Uw + wo, Ub + bo, u,
            Vw + wo, Vb + bo, v,
            Qw + wo, Qb + bo, q,
            Kw + wo, Kb + bo, k,
            nullptr, 4, 1);

        attn_hmma<<<attnGrid, 512, ATTN_SMEM>>>(q, k, v, av);

        fused_gemm<<<gemmGrid, 512, GEMM_SMEM>>>(
            av, u, hstu + bo, 1,
            f2w + wo, f2b + bo, x,
            nullptr, nullptr, nullptr,
            nullptr, nullptr, nullptr,
            nullptr, nullptr, nullptr,
            x, 1, 0);

        fused_gemm<<<gemmGrid, 512, GEMM_SMEM>>>(
            x, nullptr, ln2 + bo, 1,
            c1w + wo, c1b + bo, tb,
            nullptr, nullptr, nullptr,
            nullptr, nullptr, nullptr,
            nullptr, nullptr, nullptr,
            nullptr, 1, 2);

        fused_gemm<<<gemmGrid, 512, GEMM_SMEM>>>(
            tb, nullptr, nullptr, 0,
            c2w + wo, c2b + bo, x,
            nullptr, nullptr, nullptr,
            nullptr, nullptr, nullptr,
            nullptr, nullptr, nullptr,
            x, 1, 0);
    }

    rms_kernel<<<BT_ / 8, 256>>>(x, last_s, out);
}

// round 8
// speedup vs baseline: 2.1689x; 1.0528x over previous
#include <cuda_runtime.h>
#include <cuda_bf16.h>
#include <math.h>
#include <stdint.h>

// Problem constants
#define B_ 8
#define T_ 2048
#define D_ 128
#define L_ 4
#define H_ 2
#define HD_ 64
#define BT_ (B_ * T_)          // 16384 rows
#define EPS_ 1e-8f

#define GP 132                 // smem pitch (floats) for 128-wide gemm tiles
#define GEMM_SMEM ((2 * 128 * GP + 128) * 4)

// ---------------------------------------------------------------------------
// Scratch buffers (allocation-free: __device__ globals)
// g_q/g_k/g_v are repurposed as bf16 hi/lo pairs (each half = BT_*128 bf16)
// ---------------------------------------------------------------------------
__device__ float g_x [BT_ * D_];
__device__ float g_u [BT_ * D_];
__device__ float g_v [BT_ * D_];   // vh | vl
__device__ float g_q [BT_ * D_];   // qh | ql
__device__ float g_k [BT_ * D_];   // kh | kl
__device__ float g_av[BT_ * D_];
__device__ float g_t [BT_ * D_];

// bf16 split-output descriptor for fused_gemm
struct BfOut {
    __nv_bfloat16* hi;
    __nv_bfloat16* lo;
    float scale;
};

// ===========================================================================
// Small helpers
// ===========================================================================
__device__ __forceinline__ uint32_t smem_u32(const void* p) {
    uint32_t a;
    asm("{ .reg .u64 t; cvta.to.shared.u64 t, %1; cvt.u32.u64 %0, t; }"
        : "=r"(a) : "l"(p));
    return a;
}

// bf16 hi/lo split of an fp32 value
__device__ __forceinline__ void split_bf16(float x, __nv_bfloat16& h, __nv_bfloat16& l) {
    h = __float2bfloat16(x);
    l = __float2bfloat16(x - __bfloat162float(h));
}

__device__ __forceinline__ uint32_t bf16x2_hi(float x, float y) {
    __nv_bfloat162 t = __floats2bfloat162_rn(x, y);  // .x = x in low half
    return *reinterpret_cast<uint32_t*>(&t);
}
__device__ __forceinline__ uint32_t bf16x2_lo(float x, float y) {
    float xh = __bfloat162float(__float2bfloat16(x));
    float yh = __bfloat162float(__float2bfloat16(y));
    __nv_bfloat162 t = __floats2bfloat162_rn(x - xh, y - yh);
    return *reinterpret_cast<uint32_t*>(&t);
}

// mma.sync m16n8k16 bf16 -> f32 (accumulate in place)
__device__ __forceinline__ void mma16816(float* c, const uint32_t* a,
                                         uint32_t b0, uint32_t b1) {
    asm volatile(
        "mma.sync.aligned.m16n8k16.row.col.f32.bf16.bf16.f32 "
        "{%0,%1,%2,%3}, {%4,%5,%6,%7}, {%8,%9}, {%0,%1,%2,%3};"
        : "+f"(c[0]), "+f"(c[1]), "+f"(c[2]), "+f"(c[3])
        : "r"(a[0]), "r"(a[1]), "r"(a[2]), "r"(a[3]), "r"(b0), "r"(b1));
}

// ldmatrix x2 transposed (for V B-fragments from row-major V[key][d])
__device__ __forceinline__ void ldsm_x2_trans(uint32_t& r0, uint32_t& r1, uint32_t addr) {
    asm volatile("ldmatrix.sync.aligned.m8n8.x2.trans.shared.b16 {%0,%1}, [%2];"
                 : "=r"(r0), "=r"(r1) : "r"(addr));
}

// ===========================================================================
// Elementwise RMS kernels
// ===========================================================================
__global__ void rms_kernel(const float* __restrict__ in,
                           const float* __restrict__ sc,
                           float* __restrict__ out) {
    int warp = threadIdx.x >> 5, lane = threadIdx.x & 31;
    size_t row = (size_t)blockIdx.x * 8 + warp;
    float4 v = *(const float4*)(in + row * 128 + lane * 4);
    float ss = v.x * v.x + v.y * v.y + v.z * v.z + v.w * v.w;
    #pragma unroll
    for (int o = 16; o > 0; o >>= 1) ss += __shfl_xor_sync(0xffffffffu, ss, o);
    float r = rsqrtf(ss * (1.0f / 128.0f) + EPS_);
    float4 s = *(const float4*)(sc + lane * 4);
    *(float4*)(out + row * 128 + lane * 4) =
        make_float4(v.x * r * s.x, v.y * r * s.y, v.z * r * s.z, v.w * r * s.w);
}

__global__ void embed_rms_kernel(const int* __restrict__ seq,
                                 const float* __restrict__ item,
                                 const float* __restrict__ pos,
                                 const float* __restrict__ sc,
                                 float* __restrict__ out) {
    int warp = threadIdx.x >> 5, lane = threadIdx.x & 31;
    size_t row = (size_t)blockIdx.x * 8 + warp;
    int t = (int)(row & (T_ - 1));
    int id = seq[row];
    float4 a = *(const float4*)(item + (size_t)id * 128 + lane * 4);
    float4 p = *(const float4*)(pos + (size_t)(t + 1) * 128 + lane * 4);
    float4 v = make_float4(a.x + p.x, a.y + p.y, a.z + p.z, a.w + p.w);
    float ss = v.x * v.x + v.y * v.y + v.z * v.z + v.w * v.w;
    #pragma unroll
    for (int o = 16; o > 0; o >>= 1) ss += __shfl_xor_sync(0xffffffffu, ss, o);
    float r = rsqrtf(ss * (1.0f / 128.0f) + EPS_);
    float4 s = *(const float4*)(sc + lane * 4);
    *(float4*)(out + row * 128 + lane * 4) =
        make_float4(v.x * r * s.x, v.y * r * s.y, v.z * r * s.z, v.w * r * s.w);
}

// ===========================================================================
// Fused GEMM (fp32 SIMT). Per-weight output: fp32, or bf16 hi/lo split
// (scaled) when bf.hi != nullptr.
// ===========================================================================
__global__ void __launch_bounds__(512)
fused_gemm(const float* __restrict__ A,
           const float* __restrict__ mul,
           const float* __restrict__ scvec,
           int use_rms,
           const float* __restrict__ W0, const float* __restrict__ B0, float* __restrict__ O0,
           const float* __restrict__ W1, const float* __restrict__ B1, float* __restrict__ O1,
           const float* __restrict__ W2, const float* __restrict__ B2, float* __restrict__ O2,
           const float* __restrict__ W3, const float* __restrict__ B3, float* __restrict__ O3,
           BfOut bf0, BfOut bf1, BfOut bf2, BfOut bf3,
           const float* __restrict__ res,
           int nw, int act) {
    extern __shared__ float sm[];
    float* As = sm;
    float* Ws = As + 128 * GP;
    float* rr = Ws + 128 * GP;

    int tid = threadIdx.x;
    int row0 = blockIdx.x * 128;

    for (int idx = tid; idx < 128 * 32; idx += 512) {
        int r = idx >> 5, c4 = (idx & 31) << 2;
        *(float4*)(As + r * GP + c4) =
            *(const float4*)(A + (size_t)(row0 + r) * 128 + c4);
    }
    __syncthreads();

    if (use_rms) {
        int w = tid >> 5, lane = tid & 31;
        for (int r = w; r < 128; r += 16) {
            float4 v = *(const float4*)(As + r * GP + lane * 4);
            float ss = v.x * v.x + v.y * v.y + v.z * v.z + v.w * v.w;
            #pragma unroll
            for (int off = 16; off > 0; off >>= 1)
                ss += __shfl_xor_sync(0xffffffffu, ss, off);
            if (lane == 0) rr[r] = rsqrtf(ss * (1.0f / 128.0f) + EPS_);
        }
    } else {
        if (tid < 128) rr[tid] = 1.0f;
    }
    __syncthreads();

    if (mul) {
        for (int idx = tid; idx < 128 * 32; idx += 512) {
            int r = idx >> 5, c4 = (idx & 31) << 2;
            float4 m = *(const float4*)(mul + (size_t)(row0 + r) * 128 + c4);
            float4 a = *(float4*)(As + r * GP + c4);
            a.x *= m.x; a.y *= m.y; a.z *= m.z; a.w *= m.w;
            *(float4*)(As + r * GP + c4) = a;
        }
    }

    int ti = tid >> 4, tj = tid & 15;
    int r0 = ti * 4, c0 = tj * 8;

    const float* Wp[4] = {W0, W1, W2, W3};
    const float* Bp[4] = {B0, B1, B2, B3};
    float*       Op[4] = {O0, O1, O2, O3};
    BfOut        Bf[4] = {bf0, bf1, bf2, bf3};

    for (int wi = 0; wi < nw; wi++) {
        const float* W = Wp[wi];
        for (int idx = tid; idx < 128 * 32; idx += 512) {
            int r = idx >> 5, c4 = (idx & 31) << 2;
            float s = scvec ? scvec[r] : 1.0f;
            float4 v = *(const float4*)(W + (size_t)r * 128 + c4);
            v.x *= s; v.y *= s; v.z *= s; v.w *= s;
            *(float4*)(Ws + r * GP + c4) = v;
        }
        __syncthreads();

        float acc[4][8];
        #pragma unroll
        for (int i = 0; i < 4; i++)
            #pragma unroll
            for (int j = 0; j < 8; j++) acc[i][j] = 0.0f;

        for (int k = 0; k < 128; k += 4) {
            float4 w0[4], w1[4];
            #pragma unroll
            for (int kk = 0; kk < 4; kk++) {
                w0[kk] = *(const float4*)(Ws + (k + kk) * GP + c0);
                w1[kk] = *(const float4*)(Ws + (k + kk) * GP + c0 + 4);
            }
            #pragma unroll
            for (int i = 0; i < 4; i++) {
                float4 a = *(const float4*)(As + (r0 + i) * GP + k);
                acc[i][0] += a.x * w0[0].x + a.y * w0[1].x + a.z * w0[2].x + a.w * w0[3].x;
                acc[i][1] += a.x * w0[0].y + a.y * w0[1].y + a.z * w0[2].y + a.w * w0[3].y;
                acc[i][2] += a.x * w0[0].z + a.y * w0[1].z + a.z * w0[2].z + a.w * w0[3].z;
                acc[i][3] += a.x * w0[0].w + a.y * w0[1].w + a.z * w0[2].w + a.w * w0[3].w;
                acc[i][4] += a.x * w1[0].x + a.y * w1[1].x + a.z * w1[2].x + a.w * w1[3].x;
                acc[i][5] += a.x * w1[0].y + a.y * w1[1].y + a.z * w1[2].y + a.w * w1[3].y;
                acc[i][6] += a.x * w1[0].z + a.y * w1[1].z + a.z * w1[2].z + a.w * w1[3].z;
                acc[i][7] += a.x * w1[0].w + a.y * w1[1].w + a.z * w1[2].w + a.w * w1[3].w;
            }
        }

        const float* Bv = Bp[wi];
        float* Ov = Op[wi];
        BfOut bfo = Bf[wi];
        #pragma unroll
        for (int i = 0; i < 4; i++) {
            float rri = rr[r0 + i];
            size_t grow = (size_t)(row0 + r0 + i) * 128;
            float vout[8];
            #pragma unroll
            for (int j = 0; j < 8; j++) {
                float v = acc[i][j] * rri + Bv[c0 + j];
                if (act == 1) {
                    v = v * __fdividef(1.0f, 1.0f + __expf(-v));
                } else if (act == 2) {
                    v = 0.5f * v * (1.0f + erff(v * 0.70710678118654752f));
                }
                vout[j] = v;
            }
            if (bfo.hi) {
                __nv_bfloat16 hh[8], ll[8];
                #pragma unroll
                for (int j = 0; j < 8; j++)
                    split_bf16(vout[j] * bfo.scale, hh[j], ll[j]);
                *(uint4*)(bfo.hi + grow + c0) = *(const uint4*)hh;
                *(uint4*)(bfo.lo + grow + c0) = *(const uint4*)ll;
            } else {
                if (res) {
                    #pragma unroll
                    for (int j = 0; j < 8; j++) vout[j] += res[grow + c0 + j];
                }
                *(float4*)(Ov + grow + c0)     = make_float4(vout[0], vout[1], vout[2], vout[3]);
                *(float4*)(Ov + grow + c0 + 4) = make_float4(vout[4], vout[5], vout[6], vout[7]);
            }
        }
        __syncthreads();
    }
}

// ===========================================================================
// HMMA HSTU attention (mma.sync bf16, hi/lo 3-pass split — fp32-accurate)
// Inputs are pre-converted bf16 hi/lo (Q pre-scaled). grid = (8, 16),
// block = 512 (16 warps). Warp pair (2p, 2p+1) owns Q-rows [16p,16p+16);
// the two warps split the 128 S-columns / PV k-range (sh = warp&1).
// Block handles q-tiles qp and 15-qp (causal load balancing).
// ===========================================================================
#define QKP 72                 // row pitch in bf16 elements (144B -> conflict-free)
#define SM_QH 0
#define SM_QL 18432
#define SM_KH 36864            // reused as O-combine scratch between k-loops
#define SM_KL 55296
#define SM_VH 73728
#define SM_VL 92160
#define ATTN_SMEM 110592

__global__ void __launch_bounds__(512, 1)
attn_hmma(const __nv_bfloat16* __restrict__ Qh, const __nv_bfloat16* __restrict__ Ql,
          const __nv_bfloat16* __restrict__ Kh, const __nv_bfloat16* __restrict__ Kl,
          const __nv_bfloat16* __restrict__ Vh, const __nv_bfloat16* __restrict__ Vl,
          float* __restrict__ O) {
    extern __shared__ char smc[];
    uint32_t sb = smem_u32(smc);

    int tid  = threadIdx.x;
    int warp = tid >> 5;       // 0..15
    int lane = tid & 31;
    int pair = warp >> 1;      // 0..7
    int sh   = warp & 1;       // column half
    int g    = lane >> 2;      // fragment group row 0..7
    int c2   = lane & 3;       // fragment group col 0..3
    int m0   = pair * 16;      // pair's S/O row base (0..112)

    int bh = blockIdx.y;
    int b = bh >> 1, h = bh & 1;
    int coloff = h * HD_;
    int qp = blockIdx.x;

    for (int half = 0; half < 2; half++) {
        int qt = half ? (15 - qp) : qp;
        int qbase = b * T_ + qt * 128;

        __syncthreads();   // previous Q-tile consumers / scratch users done

        // ---- copy Q tile (bf16, already scaled+split) into smem ----
        for (int idx = tid; idx < 128 * 8; idx += 512) {
            int r = idx >> 3, c8 = (idx & 7) << 3;
            size_t goff = (size_t)(qbase + r) * 128 + coloff + c8;
            uint32_t soff = (uint32_t)(r * QKP + c8) * 2;
            *(uint4*)(smc + SM_QH + soff) = *(const uint4*)(Qh + goff);
            *(uint4*)(smc + SM_QL + soff) = *(const uint4*)(Ql + goff);
        }
        __syncthreads();

        // ---- A fragments for this pair's 16 Q rows (resident per warp) ----
        uint32_t Ah[4][4], Al[4][4];
        #pragma unroll
        for (int ks = 0; ks < 4; ks++) {
            uint32_t o00 = (uint32_t)((m0 + g)     * QKP + 16 * ks + 2 * c2) * 2;
            uint32_t o01 = (uint32_t)((m0 + g + 8) * QKP + 16 * ks + 2 * c2) * 2;
            Ah[ks][0] = *(const uint32_t*)(smc + SM_QH + o00);
            Ah[ks][1] = *(const uint32_t*)(smc + SM_QH + o01);
            Ah[ks][2] = *(const uint32_t*)(smc + SM_QH + o00 + 16);
            Ah[ks][3] = *(const uint32_t*)(smc + SM_QH + o01 + 16);
            Al[ks][0] = *(const uint32_t*)(smc + SM_QL + o00);
            Al[ks][1] = *(const uint32_t*)(smc + SM_QL + o01);
            Al[ks][2] = *(const uint32_t*)(smc + SM_QL + o00 + 16);
            Al[ks][3] = *(const uint32_t*)(smc + SM_QL + o01 + 16);
        }

        float Of[8][4];
        #pragma unroll
        for (int nf = 0; nf < 8; nf++)
            #pragma unroll
            for (int r = 0; r < 4; r++) Of[nf][r] = 0.0f;
        float ds0 = 0.0f, ds1 = 0.0f;

        int row0 = qt * 128 + m0 + g;       // global (in-seq) rows of this lane
        int row1 = row0 + 8;

        for (int kt = 0; kt <= qt; kt++) {
            int kbase = b * T_ + kt * 128;
            __syncthreads();   // previous K/V consumers done

            // ---- copy K and V tiles (bf16 hi/lo) into smem ----
            for (int idx = tid; idx < 128 * 8; idx += 512) {
                int r = idx >> 3, c8 = (idx & 7) << 3;
                size_t goff = (size_t)(kbase + r) * 128 + coloff + c8;
                uint32_t soff = (uint32_t)(r * QKP + c8) * 2;
                *(uint4*)(smc + SM_KH + soff) = *(const uint4*)(Kh + goff);
                *(uint4*)(smc + SM_KL + soff) = *(const uint4*)(Kl + goff);
                *(uint4*)(smc + SM_VH + soff) = *(const uint4*)(Vh + goff);
                *(uint4*)(smc + SM_VL + soff) = *(const uint4*)(Vl + goff);
            }
            __syncthreads();

            // ---- this warp's S-column half ----
            uint32_t Phi[4][4], Plo[4][4];

            // S = Q @ K^T for cols [64*sh, 64*sh+64), gate, pack P frags
            #pragma unroll
            for (int jj = 0; jj < 4; jj++) {
                int jpv = 4 * sh + jj;      // PV k-step index (0..7)
                #pragma unroll
                for (int e = 0; e < 2; e++) {
                    int nfr = 2 * jpv + e;  // S n-fragment (0..15)
                    float cf[4] = {0.0f, 0.0f, 0.0f, 0.0f};
                    uint32_t kb = (uint32_t)((8 * nfr + g) * QKP + 2 * c2) * 2;
                    #pragma unroll
                    for (int ks = 0; ks < 4; ks++) {
                        uint32_t o = kb + 32 * ks;
                        uint32_t bh0 = *(const uint32_t*)(smc + SM_KH + o);
                        uint32_t bh1 = *(const uint32_t*)(smc + SM_KH + o + 16);
                        uint32_t bl0 = *(const uint32_t*)(smc + SM_KL + o);
                        uint32_t bl1 = *(const uint32_t*)(smc + SM_KL + o + 16);
                        mma16816(cf, Ah[ks], bh0, bh1);
                        mma16816(cf, Ah[ks], bl0, bl1);
                        mma16816(cf, Al[ks], bh0, bh1);
                    }
                    // gate: max(silu(a),0) with causal mask (always valid)
                    int colb = kt * 128 + 8 * nfr + 2 * c2;
                    float g0 = 0.0f, g1 = 0.0f, g2 = 0.0f, g3 = 0.0f;
                    if (cf[0] > 0.0f && colb     <= row0)
                        g0 = cf[0] * __fdividef(1.0f, 1.0f + __expf(-cf[0]));
                    if (cf[1] > 0.0f && colb + 1 <= row0)
                        g1 = cf[1] * __fdividef(1.0f, 1.0f + __expf(-cf[1]));
                    if (cf[2] > 0.0f && colb     <= row1)
                        g2 = cf[2] * __fdividef(1.0f, 1.0f + __expf(-cf[2]));
                    if (cf[3] > 0.0f && colb + 1 <= row1)
                        g3 = cf[3] * __fdividef(1.0f, 1.0f + __expf(-cf[3]));
                    ds0 += g0 + g1;
                    ds1 += g2 + g3;
                    Phi[jj][2 * e]     = bf16x2_hi(g0, g1);
                    Phi[jj][2 * e + 1] = bf16x2_hi(g2, g3);
                    Plo[jj][2 * e]     = bf16x2_lo(g0, g1);
                    Plo[jj][2 * e + 1] = bf16x2_lo(g2, g3);
                }
            }

            // O += P @ V for this warp's k-half
            #pragma unroll
            for (int jj = 0; jj < 4; jj++) {
                int k0v = 16 * (4 * sh + jj);
                uint32_t rowa = (uint32_t)((k0v + (lane & 15)) * QKP) * 2;
                #pragma unroll
                for (int nf = 0; nf < 8; nf++) {
                    uint32_t addr_h = sb + SM_VH + rowa + (uint32_t)(16 * nf);
                    uint32_t addr_l = sb + SM_VL + rowa + (uint32_t)(16 * nf);
                    uint32_t vh0, vh1, vl0, vl1;
                    ldsm_x2_trans(vh0, vh1, addr_h);
                    ldsm_x2_trans(vl0, vl1, addr_l);
                    mma16816(Of[nf], Phi[jj], vh0, vh1);
                    mma16816(Of[nf], Phi[jj], vl0, vl1);
                    mma16816(Of[nf], Plo[jj], vh0, vh1);
                }
            }
        }

        // ---- quad-reduce denominators within each warp ----
        ds0 += __shfl_xor_sync(0xffffffffu, ds0, 1);
        ds0 += __shfl_xor_sync(0xffffffffu, ds0, 2);
        ds1 += __shfl_xor_sync(0xffffffffu, ds1, 1);
        ds1 += __shfl_xor_sync(0xffffffffu, ds1, 2);

        // ---- combine the two column-half partials through smem scratch ----
        __syncthreads();   // all K-smem reads done; safe to reuse as scratch
        float* scr = (float*)(smc + SM_KH + pair * 4352);
        if (sh == 1) {
            float* dst = scr + lane * 32;
            #pragma unroll
            for (int nf = 0; nf < 8; nf++) {
                dst[4 * nf + 0] = Of[nf][0];
                dst[4 * nf + 1] = Of[nf][1];
                dst[4 * nf + 2] = Of[nf][2];
                dst[4 * nf + 3] = Of[nf][3];
            }
            scr[1024 + lane * 2]     = ds0;
            scr[1024 + lane * 2 + 1] = ds1;
        }
        __syncthreads();

        if (sh == 0) {
            const float* src = scr + lane * 32;
            float dt0 = ds0 + scr[1024 + lane * 2];
            float dt1 = ds1 + scr[1024 + lane * 2 + 1];
            float f0 = (dt0 > 1e-12f) ? __fdividef(1.0f, dt0 + EPS_) : 0.0f;
            float f1 = (dt1 > 1e-12f) ? __fdividef(1.0f, dt1 + EPS_) : 0.0f;

            size_t orow0 = (size_t)(qbase + m0 + g) * 128 + coloff;
            size_t orow1 = orow0 + 8 * 128;
            #pragma unroll
            for (int nf = 0; nf < 8; nf++) {
                int c = 8 * nf + 2 * c2;
                float o0 = Of[nf][0] + src[4 * nf + 0];
                float o1 = Of[nf][1] + src[4 * nf + 1];
                float o2 = Of[nf][2] + src[4 * nf + 2];
                float o3 = Of[nf][3] + src[4 * nf + 3];
                *(float2*)(O + orow0 + c) = make_float2(o0 * f0, o1 * f0);
                *(float2*)(O + orow1 + c) = make_float2(o2 * f1, o3 * f1);
            }
        }
    }
}

// ===========================================================================
// Host orchestration
// ===========================================================================
extern "C" void kernel_launch(void* const* d_in, const int* in_sizes, int n_in,
                              void* d_out, int out_size) {
    const int*   seq    = (const int*)  d_in[0];
    // d_in[1] = attn_mask (causal tril) — synthesized in-kernel
    const float* item   = (const float*)d_in[2];
    const float* pos    = (const float*)d_in[3];
    const float* emb_s  = (const float*)d_in[4];
    const float* ln1    = (const float*)d_in[5];
    const float* Uw     = (const float*)d_in[6];
    const float* Ub     = (const float*)d_in[7];
    const float* Vw     = (const float*)d_in[8];
    const float* Vb     = (const float*)d_in[9];
    const float* Qw     = (const float*)d_in[10];
    const float* Qb     = (const float*)d_in[11];
    const float* Kw     = (const float*)d_in[12];
    const float* Kb     = (const float*)d_in[13];
    const float* f2w    = (const float*)d_in[14];
    const float* f2b    = (const float*)d_in[15];
    const float* hstu   = (const float*)d_in[16];
    const float* ln2    = (const float*)d_in[17];
    const float* c1w    = (const float*)d_in[18];
    const float* c1b    = (const float*)d_in[19];
    const float* c2w    = (const float*)d_in[20];
    const float* c2b    = (const float*)d_in[21];
    const float* last_s = (const float*)d_in[22];
    float* out = (float*)d_out;

    float *x, *u, *v, *q, *k, *av, *tb;
    cudaGetSymbolAddress((void**)&x,  g_x);
    cudaGetSymbolAddress((void**)&u,  g_u);
    cudaGetSymbolAddress((void**)&v,  g_v);
    cudaGetSymbolAddress((void**)&q,  g_q);
    cudaGetSymbolAddress((void**)&k,  g_k);
    cudaGetSymbolAddress((void**)&av, g_av);
    cudaGetSymbolAddress((void**)&tb, g_t);

    __nv_bfloat16* qh = (__nv_bfloat16*)q;
    __nv_bfloat16* ql = qh + (size_t)BT_ * 128;
    __nv_bfloat16* kh = (__nv_bfloat16*)k;
    __nv_bfloat16* kl = kh + (size_t)BT_ * 128;
    __nv_bfloat16* vh = (__nv_bfloat16*)v;
    __nv_bfloat16* vl = vh + (size_t)BT_ * 128;

    BfOut bfNone = {nullptr, nullptr, 1.0f};
    BfOut bfQ = {qh, ql, 0.125f};
    BfOut bfK = {kh, kl, 1.0f};
    BfOut bfV = {vh, vl, 1.0f};

    cudaFuncSetAttribute(fused_gemm,
                         cudaFuncAttributeMaxDynamicSharedMemorySize, GEMM_SMEM);
    cudaFuncSetAttribute(attn_hmma,
                         cudaFuncAttributeMaxDynamicSharedMemorySize, ATTN_SMEM);

    dim3 gemmGrid(BT_ / 128);
    dim3 attnGrid(8, B_ * H_);

    embed_rms_kernel<<<BT_ / 8, 256>>>(seq, item, pos, emb_s, x);

    for (int l = 0; l < L_; l++) {
        size_t wo = (size_t)l * D_ * D_;
        size_t bo = (size_t)l * D_;

        // QKVU: rms(x)*ln1 folded in; silu; U -> fp32, Q/K/V -> bf16 hi/lo
        fused_gemm<<<gemmGrid, 512, GEMM_SMEM>>>(
            x, nullptr, ln1 + bo, 1,
            Uw + wo, Ub + bo, u,
            Vw + wo, Vb + bo, nullptr,
            Qw + wo, Qb + bo, nullptr,
            Kw + wo, Kb + bo, nullptr,
            bfNone, bfV, bfQ, bfK,
            nullptr, 4, 1);

        attn_hmma<<<attnGrid, 512, ATTN_SMEM>>>(qh, ql, kh, kl, vh, vl, av);

        fused_gemm<<<gemmGrid, 512, GEMM_SMEM>>>(
            av, u, hstu + bo, 1,
            f2w + wo, f2b + bo, x,
            nullptr, nullptr, nullptr,
            nullptr, nullptr, nullptr,
            nullptr, nullptr, nullptr,
            bfNone, bfNone, bfNone, bfNone,
            x, 1, 0);

        fused_gemm<<<gemmGrid, 512, GEMM_SMEM>>>(
            x, nullptr, ln2 + bo, 1,
            c1w + wo, c1b + bo, tb,
            nullptr, nullptr, nullptr,
            nullptr, nullptr, nullptr,
            nullptr, nullptr, nullptr,
            bfNone, bfNone, bfNone, bfNone,
            nullptr, 1, 2);

        fused_gemm<<<gemmGrid, 512, GEMM_SMEM>>>(
            tb, nullptr, nullptr, 0,
            c2w + wo, c2b + bo, x,
            nullptr, nullptr, nullptr,
            nullptr, nullptr, nullptr,
            nullptr, nullptr, nullptr,
            bfNone, bfNone, bfNone, bfNone,
            x, 1, 0);
    }

    rms_kernel<<<BT_ / 8, 256>>>(x, last_s, out);
}

// round 9
// speedup vs baseline: 2.1804x; 1.0053x over previous
#include <cuda_runtime.h>
#include <cuda_bf16.h>
#include <math.h>
#include <stdint.h>

// Problem constants
#define B_ 8
#define T_ 2048
#define D_ 128
#define L_ 4
#define H_ 2
#define HD_ 64
#define BT_ (B_ * T_)          // 16384 rows
#define EPS_ 1e-8f

#define GP 132                 // smem pitch (floats) for 128-wide gemm tiles
#define GEMM_SMEM ((2 * 128 * GP + 128) * 4)

// ---------------------------------------------------------------------------
// Scratch buffers (allocation-free: __device__ globals)
// g_q/g_k/g_v are repurposed as bf16 hi/lo pairs (each half = BT_*128 bf16)
// ---------------------------------------------------------------------------
__device__ float g_x [BT_ * D_];
__device__ float g_u [BT_ * D_];
__device__ float g_v [BT_ * D_];   // vh | vl
__device__ float g_q [BT_ * D_];   // qh | ql
__device__ float g_k [BT_ * D_];   // kh | kl
__device__ float g_av[BT_ * D_];
__device__ float g_t [BT_ * D_];

// bf16 split-output descriptor for fused_gemm
struct BfOut {
    __nv_bfloat16* hi;
    __nv_bfloat16* lo;
    float scale;
};

// ===========================================================================
// Small helpers
// ===========================================================================
__device__ __forceinline__ uint32_t smem_u32(const void* p) {
    uint32_t a;
    asm("{ .reg .u64 t; cvta.to.shared.u64 t, %1; cvt.u32.u64 %0, t; }"
        : "=r"(a) : "l"(p));
    return a;
}

#define CP16(saddr, gptr) \
    asm volatile("cp.async.cg.shared.global [%0], [%1], 16;" \
                 :: "r"((uint32_t)(saddr)), "l"(gptr) : "memory")
#define CP_COMMIT() asm volatile("cp.async.commit_group;" ::: "memory")
#define CP_WAIT0()  asm volatile("cp.async.wait_group 0;" ::: "memory")

// bf16 hi/lo split of an fp32 value
__device__ __forceinline__ void split_bf16(float x, __nv_bfloat16& h, __nv_bfloat16& l) {
    h = __float2bfloat16(x);
    l = __float2bfloat16(x - __bfloat162float(h));
}

__device__ __forceinline__ uint32_t bf16x2_hi(float x, float y) {
    __nv_bfloat162 t = __floats2bfloat162_rn(x, y);  // .x = x in low half
    return *reinterpret_cast<uint32_t*>(&t);
}
__device__ __forceinline__ uint32_t bf16x2_lo(float x, float y) {
    float xh = __bfloat162float(__float2bfloat16(x));
    float yh = __bfloat162float(__float2bfloat16(y));
    __nv_bfloat162 t = __floats2bfloat162_rn(x - xh, y - yh);
    return *reinterpret_cast<uint32_t*>(&t);
}

// mma.sync m16n8k16 bf16 -> f32 (accumulate in place)
__device__ __forceinline__ void mma16816(float* c, const uint32_t* a,
                                         uint32_t b0, uint32_t b1) {
    asm volatile(
        "mma.sync.aligned.m16n8k16.row.col.f32.bf16.bf16.f32 "
        "{%0,%1,%2,%3}, {%4,%5,%6,%7}, {%8,%9}, {%0,%1,%2,%3};"
        : "+f"(c[0]), "+f"(c[1]), "+f"(c[2]), "+f"(c[3])
        : "r"(a[0]), "r"(a[1]), "r"(a[2]), "r"(a[3]), "r"(b0), "r"(b1));
}

// ldmatrix x2 transposed (for V B-fragments from row-major V[key][d])
__device__ __forceinline__ void ldsm_x2_trans(uint32_t& r0, uint32_t& r1, uint32_t addr) {
    asm volatile("ldmatrix.sync.aligned.m8n8.x2.trans.shared.b16 {%0,%1}, [%2];"
                 : "=r"(r0), "=r"(r1) : "r"(addr));
}

// ===========================================================================
// Elementwise RMS kernels
// ===========================================================================
__global__ void rms_kernel(const float* __restrict__ in,
                           const float* __restrict__ sc,
                           float* __restrict__ out) {
    int warp = threadIdx.x >> 5, lane = threadIdx.x & 31;
    size_t row = (size_t)blockIdx.x * 8 + warp;
    float4 v = *(const float4*)(in + row * 128 + lane * 4);
    float ss = v.x * v.x + v.y * v.y + v.z * v.z + v.w * v.w;
    #pragma unroll
    for (int o = 16; o > 0; o >>= 1) ss += __shfl_xor_sync(0xffffffffu, ss, o);
    float r = rsqrtf(ss * (1.0f / 128.0f) + EPS_);
    float4 s = *(const float4*)(sc + lane * 4);
    *(float4*)(out + row * 128 + lane * 4) =
        make_float4(v.x * r * s.x, v.y * r * s.y, v.z * r * s.z, v.w * r * s.w);
}

__global__ void embed_rms_kernel(const int* __restrict__ seq,
                                 const float* __restrict__ item,
                                 const float* __restrict__ pos,
                                 const float* __restrict__ sc,
                                 float* __restrict__ out) {
    int warp = threadIdx.x >> 5, lane = threadIdx.x & 31;
    size_t row = (size_t)blockIdx.x * 8 + warp;
    int t = (int)(row & (T_ - 1));
    int id = seq[row];
    float4 a = *(const float4*)(item + (size_t)id * 128 + lane * 4);
    float4 p = *(const float4*)(pos + (size_t)(t + 1) * 128 + lane * 4);
    float4 v = make_float4(a.x + p.x, a.y + p.y, a.z + p.z, a.w + p.w);
    float ss = v.x * v.x + v.y * v.y + v.z * v.z + v.w * v.w;
    #pragma unroll
    for (int o = 16; o > 0; o >>= 1) ss += __shfl_xor_sync(0xffffffffu, ss, o);
    float r = rsqrtf(ss * (1.0f / 128.0f) + EPS_);
    float4 s = *(const float4*)(sc + lane * 4);
    *(float4*)(out + row * 128 + lane * 4) =
        make_float4(v.x * r * s.x, v.y * r * s.y, v.z * r * s.z, v.w * r * s.w);
}

// ===========================================================================
// Fused GEMM (fp32 SIMT). Per-weight output: fp32, or bf16 hi/lo split
// (scaled) when bf.hi != nullptr.
// ===========================================================================
__global__ void __launch_bounds__(512)
fused_gemm(const float* __restrict__ A,
           const float* __restrict__ mul,
           const float* __restrict__ scvec,
           int use_rms,
           const float* __restrict__ W0, const float* __restrict__ B0, float* __restrict__ O0,
           const float* __restrict__ W1, const float* __restrict__ B1, float* __restrict__ O1,
           const float* __restrict__ W2, const float* __restrict__ B2, float* __restrict__ O2,
           const float* __restrict__ W3, const float* __restrict__ B3, float* __restrict__ O3,
           BfOut bf0, BfOut bf1, BfOut bf2, BfOut bf3,
           const float* __restrict__ res,
           int nw, int act) {
    extern __shared__ float sm[];
    float* As = sm;
    float* Ws = As + 128 * GP;
    float* rr = Ws + 128 * GP;

    int tid = threadIdx.x;
    int row0 = blockIdx.x * 128;

    for (int idx = tid; idx < 128 * 32; idx += 512) {
        int r = idx >> 5, c4 = (idx & 31) << 2;
        *(float4*)(As + r * GP + c4) =
            *(const float4*)(A + (size_t)(row0 + r) * 128 + c4);
    }
    __syncthreads();

    if (use_rms) {
        int w = tid >> 5, lane = tid & 31;
        for (int r = w; r < 128; r += 16) {
            float4 v = *(const float4*)(As + r * GP + lane * 4);
            float ss = v.x * v.x + v.y * v.y + v.z * v.z + v.w * v.w;
            #pragma unroll
            for (int off = 16; off > 0; off >>= 1)
                ss += __shfl_xor_sync(0xffffffffu, ss, off);
            if (lane == 0) rr[r] = rsqrtf(ss * (1.0f / 128.0f) + EPS_);
        }
    } else {
        if (tid < 128) rr[tid] = 1.0f;
    }
    __syncthreads();

    if (mul) {
        for (int idx = tid; idx < 128 * 32; idx += 512) {
            int r = idx >> 5, c4 = (idx & 31) << 2;
            float4 m = *(const float4*)(mul + (size_t)(row0 + r) * 128 + c4);
            float4 a = *(float4*)(As + r * GP + c4);
            a.x *= m.x; a.y *= m.y; a.z *= m.z; a.w *= m.w;
            *(float4*)(As + r * GP + c4) = a;
        }
    }

    int ti = tid >> 4, tj = tid & 15;
    int r0 = ti * 4, c0 = tj * 8;

    const float* Wp[4] = {W0, W1, W2, W3};
    const float* Bp[4] = {B0, B1, B2, B3};
    float*       Op[4] = {O0, O1, O2, O3};
    BfOut        Bf[4] = {bf0, bf1, bf2, bf3};

    for (int wi = 0; wi < nw; wi++) {
        const float* W = Wp[wi];
        for (int idx = tid; idx < 128 * 32; idx += 512) {
            int r = idx >> 5, c4 = (idx & 31) << 2;
            float s = scvec ? scvec[r] : 1.0f;
            float4 v = *(const float4*)(W + (size_t)r * 128 + c4);
            v.x *= s; v.y *= s; v.z *= s; v.w *= s;
            *(float4*)(Ws + r * GP + c4) = v;
        }
        __syncthreads();

        float acc[4][8];
        #pragma unroll
        for (int i = 0; i < 4; i++)
            #pragma unroll
            for (int j = 0; j < 8; j++) acc[i][j] = 0.0f;

        for (int k = 0; k < 128; k += 4) {
            float4 w0[4], w1[4];
            #pragma unroll
            for (int kk = 0; kk < 4; kk++) {
                w0[kk] = *(const float4*)(Ws + (k + kk) * GP + c0);
                w1[kk] = *(const float4*)(Ws + (k + kk) * GP + c0 + 4);
            }
            #pragma unroll
            for (int i = 0; i < 4; i++) {
                float4 a = *(const float4*)(As + (r0 + i) * GP + k);
                acc[i][0] += a.x * w0[0].x + a.y * w0[1].x + a.z * w0[2].x + a.w * w0[3].x;
                acc[i][1] += a.x * w0[0].y + a.y * w0[1].y + a.z * w0[2].y + a.w * w0[3].y;
                acc[i][2] += a.x * w0[0].z + a.y * w0[1].z + a.z * w0[2].z + a.w * w0[3].z;
                acc[i][3] += a.x * w0[0].w + a.y * w0[1].w + a.z * w0[2].w + a.w * w0[3].w;
                acc[i][4] += a.x * w1[0].x + a.y * w1[1].x + a.z * w1[2].x + a.w * w1[3].x;
                acc[i][5] += a.x * w1[0].y + a.y * w1[1].y + a.z * w1[2].y + a.w * w1[3].y;
                acc[i][6] += a.x * w1[0].z + a.y * w1[1].z + a.z * w1[2].z + a.w * w1[3].z;
                acc[i][7] += a.x * w1[0].w + a.y * w1[1].w + a.z * w1[2].w + a.w * w1[3].w;
            }
        }

        const float* Bv = Bp[wi];
        float* Ov = Op[wi];
        BfOut bfo = Bf[wi];
        #pragma unroll
        for (int i = 0; i < 4; i++) {
            float rri = rr[r0 + i];
            size_t grow = (size_t)(row0 + r0 + i) * 128;
            float vout[8];
            #pragma unroll
            for (int j = 0; j < 8; j++) {
                float v = acc[i][j] * rri + Bv[c0 + j];
                if (act == 1) {
                    v = v * __fdividef(1.0f, 1.0f + __expf(-v));
                } else if (act == 2) {
                    v = 0.5f * v * (1.0f + erff(v * 0.70710678118654752f));
                }
                vout[j] = v;
            }
            if (bfo.hi) {
                __nv_bfloat16 hh[8], ll[8];
                #pragma unroll
                for (int j = 0; j < 8; j++)
                    split_bf16(vout[j] * bfo.scale, hh[j], ll[j]);
                *(uint4*)(bfo.hi + grow + c0) = *(const uint4*)hh;
                *(uint4*)(bfo.lo + grow + c0) = *(const uint4*)ll;
            } else {
                if (res) {
                    #pragma unroll
                    for (int j = 0; j < 8; j++) vout[j] += res[grow + c0 + j];
                }
                *(float4*)(Ov + grow + c0)     = make_float4(vout[0], vout[1], vout[2], vout[3]);
                *(float4*)(Ov + grow + c0 + 4) = make_float4(vout[4], vout[5], vout[6], vout[7]);
            }
        }
        __syncthreads();
    }
}

// ===========================================================================
// HMMA HSTU attention, double-buffered cp.async pipeline.
// Inputs pre-converted bf16 hi/lo (Q pre-scaled). grid = (8, 16), block = 512.
// Warp pair (2p, 2p+1) owns Q-rows [16p,16p+16); warps split S-cols (sh).
// Block handles q-tiles qp and 15-qp (causal load balancing).
// ===========================================================================
#define QKP 72                 // row pitch in bf16 elements (144B -> conflict-free)
#define TILEB 18432            // one 128 x QKP bf16 tile
#define SM_QH  0
#define SM_QL  (TILEB)
#define SM_K0H (2 * TILEB)     // buf0 K hi (reused as combine scratch at end)
#define SM_K0L (3 * TILEB)
#define SM_V0H (4 * TILEB)
#define SM_V0L (5 * TILEB)
#define SM_K1H (6 * TILEB)
#define SM_K1L (7 * TILEB)
#define SM_V1H (8 * TILEB)
#define SM_V1L (9 * TILEB)
#define ATTN_SMEM (10 * TILEB)   // 184320 bytes

__global__ void __launch_bounds__(512, 1)
attn_hmma(const __nv_bfloat16* __restrict__ Qh, const __nv_bfloat16* __restrict__ Ql,
          const __nv_bfloat16* __restrict__ Kh, const __nv_bfloat16* __restrict__ Kl,
          const __nv_bfloat16* __restrict__ Vh, const __nv_bfloat16* __restrict__ Vl,
          float* __restrict__ O) {
    extern __shared__ char smc[];
    uint32_t sb = smem_u32(smc);

    int tid  = threadIdx.x;
    int warp = tid >> 5;       // 0..15
    int lane = tid & 31;
    int pair = warp >> 1;      // 0..7
    int sh   = warp & 1;       // column half
    int g    = lane >> 2;      // fragment group row 0..7
    int c2   = lane & 3;       // fragment group col 0..3
    int m0   = pair * 16;      // pair's S/O row base (0..112)

    int bh = blockIdx.y;
    int b = bh >> 1, h = bh & 1;
    int coloff = h * HD_;
    int qp = blockIdx.x;

    const uint32_t KHo[2] = {sb + SM_K0H, sb + SM_K1H};
    const uint32_t KLo[2] = {sb + SM_K0L, sb + SM_K1L};
    const uint32_t VHo[2] = {sb + SM_V0H, sb + SM_V1H};
    const uint32_t VLo[2] = {sb + SM_V0L, sb + SM_V1L};

    for (int half = 0; half < 2; half++) {
        int qt = half ? (15 - qp) : qp;
        int qbase = b * T_ + qt * 128;

        __syncthreads();   // previous q-tile consumers / scratch users done

        // ---- async copy: Q tile + K/V tile 0 ----
        for (int idx = tid; idx < 128 * 8; idx += 512) {
            int r = idx >> 3, c8 = (idx & 7) << 3;
            size_t goff = (size_t)(qbase + r) * 128 + coloff + c8;
            uint32_t soff = (uint32_t)(r * QKP + c8) * 2;
            CP16(sb + SM_QH + soff, Qh + goff);
            CP16(sb + SM_QL + soff, Ql + goff);
        }
        {
            int kbase0 = b * T_;   // kt = 0
            for (int idx = tid; idx < 128 * 8; idx += 512) {
                int r = idx >> 3, c8 = (idx & 7) << 3;
                size_t goff = (size_t)(kbase0 + r) * 128 + coloff + c8;
                uint32_t soff = (uint32_t)(r * QKP + c8) * 2;
                CP16(KHo[0] + soff, Kh + goff);
                CP16(KLo[0] + soff, Kl + goff);
                CP16(VHo[0] + soff, Vh + goff);
                CP16(VLo[0] + soff, Vl + goff);
            }
        }
        CP_COMMIT();
        CP_WAIT0();
        __syncthreads();

        // ---- A fragments for this pair's 16 Q rows (resident per warp) ----
        uint32_t Ah[4][4], Al[4][4];
        #pragma unroll
        for (int ks = 0; ks < 4; ks++) {
            uint32_t o00 = (uint32_t)((m0 + g)     * QKP + 16 * ks + 2 * c2) * 2;
            uint32_t o01 = (uint32_t)((m0 + g + 8) * QKP + 16 * ks + 2 * c2) * 2;
            Ah[ks][0] = *(const uint32_t*)(smc + SM_QH + o00);
            Ah[ks][1] = *(const uint32_t*)(smc + SM_QH + o01);
            Ah[ks][2] = *(const uint32_t*)(smc + SM_QH + o00 + 16);
            Ah[ks][3] = *(const uint32_t*)(smc + SM_QH + o01 + 16);
            Al[ks][0] = *(const uint32_t*)(smc + SM_QL + o00);
            Al[ks][1] = *(const uint32_t*)(smc + SM_QL + o01);
            Al[ks][2] = *(const uint32_t*)(smc + SM_QL + o00 + 16);
            Al[ks][3] = *(const uint32_t*)(smc + SM_QL + o01 + 16);
        }

        float Of[8][4];
        #pragma unroll
        for (int nf = 0; nf < 8; nf++)
            #pragma unroll
            for (int r = 0; r < 4; r++) Of[nf][r] = 0.0f;
        float ds0 = 0.0f, ds1 = 0.0f;

        int row0 = qt * 128 + m0 + g;       // global (in-seq) rows of this lane
        int row1 = row0 + 8;

        for (int kt = 0; kt <= qt; kt++) {
            int p = kt & 1;

            // ---- prefetch tile kt+1 into the other buffer ----
            if (kt < qt) {
                int kb1 = b * T_ + (kt + 1) * 128;
                int q1 = (kt + 1) & 1;
                for (int idx = tid; idx < 128 * 8; idx += 512) {
                    int r = idx >> 3, c8 = (idx & 7) << 3;
                    size_t goff = (size_t)(kb1 + r) * 128 + coloff + c8;
                    uint32_t soff = (uint32_t)(r * QKP + c8) * 2;
                    CP16(KHo[q1] + soff, Kh + goff);
                    CP16(KLo[q1] + soff, Kl + goff);
                    CP16(VHo[q1] + soff, Vh + goff);
                    CP16(VLo[q1] + soff, Vl + goff);
                }
                CP_COMMIT();
            }

            const char* kh_s = (const char*)smc + (KHo[p] - sb);
            const char* kl_s = (const char*)smc + (KLo[p] - sb);
            uint32_t vh_b = VHo[p];
            uint32_t vl_b = VLo[p];

            // ---- this warp's S-column half ----
            uint32_t Phi[4][4], Plo[4][4];

            #pragma unroll
            for (int jj = 0; jj < 4; jj++) {
                int jpv = 4 * sh + jj;      // PV k-step index (0..7)
                #pragma unroll
                for (int e = 0; e < 2; e++) {
                    int nfr = 2 * jpv + e;  // S n-fragment (0..15)
                    float cf[4] = {0.0f, 0.0f, 0.0f, 0.0f};
                    uint32_t kb = (uint32_t)((8 * nfr + g) * QKP + 2 * c2) * 2;
                    #pragma unroll
                    for (int ks = 0; ks < 4; ks++) {
                        uint32_t o = kb + 32 * ks;
                        uint32_t bh0 = *(const uint32_t*)(kh_s + o);
                        uint32_t bh1 = *(const uint32_t*)(kh_s + o + 16);
                        uint32_t bl0 = *(const uint32_t*)(kl_s + o);
                        uint32_t bl1 = *(const uint32_t*)(kl_s + o + 16);
                        mma16816(cf, Ah[ks], bh0, bh1);
                        mma16816(cf, Ah[ks], bl0, bl1);
                        mma16816(cf, Al[ks], bh0, bh1);
                    }
                    // gate: max(silu(a),0) with causal mask (always valid)
                    int colb = kt * 128 + 8 * nfr + 2 * c2;
                    float g0 = 0.0f, g1 = 0.0f, g2 = 0.0f, g3 = 0.0f;
                    if (cf[0] > 0.0f && colb     <= row0)
                        g0 = cf[0] * __fdividef(1.0f, 1.0f + __expf(-cf[0]));
                    if (cf[1] > 0.0f && colb + 1 <= row0)
                        g1 = cf[1] * __fdividef(1.0f, 1.0f + __expf(-cf[1]));
                    if (cf[2] > 0.0f && colb     <= row1)
                        g2 = cf[2] * __fdividef(1.0f, 1.0f + __expf(-cf[2]));
                    if (cf[3] > 0.0f && colb + 1 <= row1)
                        g3 = cf[3] * __fdividef(1.0f, 1.0f + __expf(-cf[3]));
                    ds0 += g0 + g1;
                    ds1 += g2 + g3;
                    Phi[jj][2 * e]     = bf16x2_hi(g0, g1);
                    Phi[jj][2 * e + 1] = bf16x2_hi(g2, g3);
                    Plo[jj][2 * e]     = bf16x2_lo(g0, g1);
                    Plo[jj][2 * e + 1] = bf16x2_lo(g2, g3);
                }
            }

            // O += P @ V for this warp's k-half
            #pragma unroll
            for (int jj = 0; jj < 4; jj++) {
                int k0v = 16 * (4 * sh + jj);
                uint32_t rowa = (uint32_t)((k0v + (lane & 15)) * QKP) * 2;
                #pragma unroll
                for (int nf = 0; nf < 8; nf++) {
                    uint32_t vh0, vh1, vl0, vl1;
                    ldsm_x2_trans(vh0, vh1, vh_b + rowa + (uint32_t)(16 * nf));
                    ldsm_x2_trans(vl0, vl1, vl_b + rowa + (uint32_t)(16 * nf));
                    mma16816(Of[nf], Phi[jj], vh0, vh1);
                    mma16816(Of[nf], Phi[jj], vl0, vl1);
                    mma16816(Of[nf], Plo[jj], vh0, vh1);
                }
            }

            CP_WAIT0();        // prefetched tile resident
            __syncthreads();   // all warps done reading buffer p
        }

        // ---- quad-reduce denominators within each warp ----
        ds0 += __shfl_xor_sync(0xffffffffu, ds0, 1);
        ds0 += __shfl_xor_sync(0xffffffffu, ds0, 2);
        ds1 += __shfl_xor_sync(0xffffffffu, ds1, 1);
        ds1 += __shfl_xor_sync(0xffffffffu, ds1, 2);

        // ---- combine the two column-half partials (scratch in K0 region) ----
        float* scr = (float*)(smc + SM_K0H + pair * 4352);
        if (sh == 1) {
            float* dst = scr + lane * 32;
            #pragma unroll
            for (int nf = 0; nf < 8; nf++) {
                dst[4 * nf + 0] = Of[nf][0];
                dst[4 * nf + 1] = Of[nf][1];
                dst[4 * nf + 2] = Of[nf][2];
                dst[4 * nf + 3] = Of[nf][3];
            }
            scr[1024 + lane * 2]     = ds0;
            scr[1024 + lane * 2 + 1] = ds1;
        }
        __syncthreads();

        if (sh == 0) {
            const float* src = scr + lane * 32;
            float dt0 = ds0 + scr[1024 + lane * 2];
            float dt1 = ds1 + scr[1024 + lane * 2 + 1];
            float f0 = (dt0 > 1e-12f) ? __fdividef(1.0f, dt0 + EPS_) : 0.0f;
            float f1 = (dt1 > 1e-12f) ? __fdividef(1.0f, dt1 + EPS_) : 0.0f;

            size_t orow0 = (size_t)(qbase + m0 + g) * 128 + coloff;
            size_t orow1 = orow0 + 8 * 128;
            #pragma unroll
            for (int nf = 0; nf < 8; nf++) {
                int c = 8 * nf + 2 * c2;
                float o0 = Of[nf][0] + src[4 * nf + 0];
                float o1 = Of[nf][1] + src[4 * nf + 1];
                float o2 = Of[nf][2] + src[4 * nf + 2];
                float o3 = Of[nf][3] + src[4 * nf + 3];
                *(float2*)(O + orow0 + c) = make_float2(o0 * f0, o1 * f0);
                *(float2*)(O + orow1 + c) = make_float2(o2 * f1, o3 * f1);
            }
        }
    }
}

// ===========================================================================
// Host orchestration
// ===========================================================================
extern "C" void kernel_launch(void* const* d_in, const int* in_sizes, int n_in,
                              void* d_out, int out_size) {
    const int*   seq    = (const int*)  d_in[0];
    // d_in[1] = attn_mask (causal tril) — synthesized in-kernel
    const float* item   = (const float*)d_in[2];
    const float* pos    = (const float*)d_in[3];
    const float* emb_s  = (const float*)d_in[4];
    const float* ln1    = (const float*)d_in[5];
    const float* Uw     = (const float*)d_in[6];
    const float* Ub     = (const float*)d_in[7];
    const float* Vw     = (const float*)d_in[8];
    const float* Vb     = (const float*)d_in[9];
    const float* Qw     = (const float*)d_in[10];
    const float* Qb     = (const float*)d_in[11];
    const float* Kw     = (const float*)d_in[12];
    const float* Kb     = (const float*)d_in[13];
    const float* f2w    = (const float*)d_in[14];
    const float* f2b    = (const float*)d_in[15];
    const float* hstu   = (const float*)d_in[16];
    const float* ln2    = (const float*)d_in[17];
    const float* c1w    = (const float*)d_in[18];
    const float* c1b    = (const float*)d_in[19];
    const float* c2w    = (const float*)d_in[20];
    const float* c2b    = (const float*)d_in[21];
    const float* last_s = (const float*)d_in[22];
    float* out = (float*)d_out;

    float *x, *u, *v, *q, *k, *av, *tb;
    cudaGetSymbolAddress((void**)&x,  g_x);
    cudaGetSymbolAddress((void**)&u,  g_u);
    cudaGetSymbolAddress((void**)&v,  g_v);
    cudaGetSymbolAddress((void**)&q,  g_q);
    cudaGetSymbolAddress((void**)&k,  g_k);
    cudaGetSymbolAddress((void**)&av, g_av);
    cudaGetSymbolAddress((void**)&tb, g_t);

    __nv_bfloat16* qh = (__nv_bfloat16*)q;
    __nv_bfloat16* ql = qh + (size_t)BT_ * 128;
    __nv_bfloat16* kh = (__nv_bfloat16*)k;
    __nv_bfloat16* kl = kh + (size_t)BT_ * 128;
    __nv_bfloat16* vh = (__nv_bfloat16*)v;
    __nv_bfloat16* vl = vh + (size_t)BT_ * 128;

    BfOut bfNone = {nullptr, nullptr, 1.0f};
    BfOut bfQ = {qh, ql, 0.125f};
    BfOut bfK = {kh, kl, 1.0f};
    BfOut bfV = {vh, vl, 1.0f};

    cudaFuncSetAttribute(fused_gemm,
                         cudaFuncAttributeMaxDynamicSharedMemorySize, GEMM_SMEM);
    cudaFuncSetAttribute(attn_hmma,
                         cudaFuncAttributeMaxDynamicSharedMemorySize, ATTN_SMEM);

    dim3 gemmGrid(BT_ / 128);
    dim3 attnGrid(8, B_ * H_);

    embed_rms_kernel<<<BT_ / 8, 256>>>(seq, item, pos, emb_s, x);

    for (int l = 0; l < L_; l++) {
        size_t wo = (size_t)l * D_ * D_;
        size_t bo = (size_t)l * D_;

        // QKVU: rms(x)*ln1 folded in; silu; U -> fp32, Q/K/V -> bf16 hi/lo
        fused_gemm<<<gemmGrid, 512, GEMM_SMEM>>>(
            x, nullptr, ln1 + bo, 1,
            Uw + wo, Ub + bo, u,
            Vw + wo, Vb + bo, nullptr,
            Qw + wo, Qb + bo, nullptr,
            Kw + wo, Kb + bo, nullptr,
            bfNone, bfV, bfQ, bfK,
            nullptr, 4, 1);

        attn_hmma<<<attnGrid, 512, ATTN_SMEM>>>(qh, ql, kh, kl, vh, vl, av);

        fused_gemm<<<gemmGrid, 512, GEMM_SMEM>>>(
            av, u, hstu + bo, 1,
            f2w + wo, f2b + bo, x,
            nullptr, nullptr, nullptr,
            nullptr, nullptr, nullptr,
            nullptr, nullptr, nullptr,
            bfNone, bfNone, bfNone, bfNone,
            x, 1, 0);

        fused_gemm<<<gemmGrid, 512, GEMM_SMEM>>>(
            x, nullptr, ln2 + bo, 1,
            c1w + wo, c1b + bo, tb,
            nullptr, nullptr, nullptr,
            nullptr, nullptr, nullptr,
            nullptr, nullptr, nullptr,
            bfNone, bfNone, bfNone, bfNone,
            nullptr, 1, 2);

        fused_gemm<<<gemmGrid, 512, GEMM_SMEM>>>(
            tb, nullptr, nullptr, 0,
            c2w + wo, c2b + bo, x,
            nullptr, nullptr, nullptr,
            nullptr, nullptr, nullptr,
            nullptr, nullptr, nullptr,
            bfNone, bfNone, bfNone, bfNone,
            x, 1, 0);
    }

    rms_kernel<<<BT_ / 8, 256>>>(x, last_s, out);
}